// round 12
// baseline (speedup 1.0000x reference)
#include <cuda_runtime.h>
#include <cuda_bf16.h>
#include <cstdint>
#include <stdint.h>
#include <math.h>

// ---------------- problem constants ----------------
#define B    4
#define LQ   1024
#define LK   2048
#define D    1024
#define H    16
#define HD   64
#define F    4096
#define MQ   (B*LQ)     // 4096
#define MCTX (B*LK)     // 8192

// ---------------- scratch (static __device__, no allocs) ----------------
__device__ float g_q   [(size_t)MQ   * D];
__device__ float g_k   [(size_t)MCTX * D];
__device__ float g_v   [(size_t)MCTX * D];
__device__ float g_att [(size_t)MQ * D];
__device__ float g_x   [(size_t)MQ * D];
__device__ float g_x2  [(size_t)MQ * D];
__device__ float g_y   [(size_t)MQ * D];
__device__ float g_int [(size_t)MQ * F];
__device__ __nv_bfloat16 g_sa [(size_t)MQ * 3 * F];      // A' split buffer
__device__ __nv_bfloat16 g_sb [(size_t)3 * F * D];       // B' split buffer

// ---------------- asm helpers ----------------
__device__ __forceinline__ unsigned smem_u32(const void* p) {
    return (unsigned)__cvta_generic_to_shared(p);
}

#define LDSM4(R0,R1,R2,R3,PTR) do { \
    unsigned _a = smem_u32(PTR); \
    asm volatile("ldmatrix.sync.aligned.m8n8.x4.shared.b16 {%0,%1,%2,%3}, [%4];" \
        : "=r"(R0),"=r"(R1),"=r"(R2),"=r"(R3) : "r"(_a)); } while(0)

#define LDSM4T(R0,R1,R2,R3,PTR) do { \
    unsigned _a = smem_u32(PTR); \
    asm volatile("ldmatrix.sync.aligned.m8n8.x4.trans.shared.b16 {%0,%1,%2,%3}, [%4];" \
        : "=r"(R0),"=r"(R1),"=r"(R2),"=r"(R3) : "r"(_a)); } while(0)

#define MMA16816(C,A0,A1,A2,A3,B0,B1) \
    asm volatile("mma.sync.aligned.m16n8k16.row.col.f32.bf16.bf16.f32 " \
        "{%0,%1,%2,%3},{%4,%5,%6,%7},{%8,%9},{%0,%1,%2,%3};" \
        : "+f"((C)[0]), "+f"((C)[1]), "+f"((C)[2]), "+f"((C)[3]) \
        : "r"(A0), "r"(A1), "r"(A2), "r"(A3), "r"(B0), "r"(B1))

__device__ __forceinline__ void cp_async16(void* smem, const void* gmem) {
    unsigned s = smem_u32(smem);
    asm volatile("cp.async.cg.shared.global [%0], [%1], 16;\n" :: "r"(s), "l"(gmem));
}

// ================= bf16 split conversion (GEMM operands) =================
__global__ void __launch_bounds__(256) split_a_kernel(
    const float* __restrict__ X, __nv_bfloat16* __restrict__ Y, int cmask, int cshift)
{
    const size_t i4 = ((size_t)blockIdx.x * 256 + threadIdx.x) * 4;
    const int C = cmask + 1;
    const size_t r = i4 >> cshift;
    const int c = (int)(i4 & cmask);
    float4 x = *(const float4*)(X + i4);
    float xs[4] = {x.x, x.y, x.z, x.w};
    unsigned short hu[4], lu[4];
    #pragma unroll
    for (int t = 0; t < 4; t++) {
        __nv_bfloat16 hh = __float2bfloat16(xs[t]);
        __nv_bfloat16 ll = __float2bfloat16(xs[t] - __bfloat162float(hh));
        hu[t] = *(unsigned short*)&hh; lu[t] = *(unsigned short*)&ll;
    }
    ushort4 h4 = {hu[0], hu[1], hu[2], hu[3]};
    ushort4 l4 = {lu[0], lu[1], lu[2], lu[3]};
    __nv_bfloat16* row = Y + r * (size_t)(3 * C);
    *(ushort4*)(row + c)         = h4;
    *(ushort4*)(row + C + c)     = h4;
    *(ushort4*)(row + 2 * C + c) = l4;
}

__global__ void __launch_bounds__(256) split_b_kernel(
    const float* __restrict__ W, __nv_bfloat16* __restrict__ Y, int K, int nmask, int nshift)
{
    const size_t i4 = ((size_t)blockIdx.x * 256 + threadIdx.x) * 4;
    const int N = nmask + 1;
    const size_t r = i4 >> nshift;
    const int c = (int)(i4 & nmask);
    float4 x = *(const float4*)(W + i4);
    float xs[4] = {x.x, x.y, x.z, x.w};
    unsigned short hu[4], lu[4];
    #pragma unroll
    for (int t = 0; t < 4; t++) {
        __nv_bfloat16 hh = __float2bfloat16(xs[t]);
        __nv_bfloat16 ll = __float2bfloat16(xs[t] - __bfloat162float(hh));
        hu[t] = *(unsigned short*)&hh; lu[t] = *(unsigned short*)&ll;
    }
    ushort4 h4 = {hu[0], hu[1], hu[2], hu[3]};
    ushort4 l4 = {lu[0], lu[1], lu[2], lu[3]};
    *(ushort4*)(Y + r * (size_t)N + c)             = h4;  // Bh
    *(ushort4*)(Y + ((size_t)K + r) * N + c)       = l4;  // Bl
    *(ushort4*)(Y + ((size_t)(2 * K) + r) * N + c) = h4;  // Bh
}

// ================= bf16 tensor-core GEMM (BM=256, BN=128, BK=32) =================
// 8 warps as 4x2; warp tile 64x64 (f=4 m16 frags x p=8 n8 frags).
#define HG_ABUF 20480               // 256 rows x 40 halves x 2B
#define HG_BBUF 8704                // 32 rows x 136 halves x 2B
#define HG_B0   (2 * HG_ABUF)       // 40960
#define HG_SMEM (2 * HG_ABUF + 2 * HG_BBUF)   // 58368

template<int EPI>  // 0 = bias, 1 = bias + exact gelu
__global__ void __launch_bounds__(256) hgemm_kernel(
    const __nv_bfloat16* __restrict__ A, const __nv_bfloat16* __restrict__ Bw,
    const float* __restrict__ bias, float* __restrict__ C,
    int N, int Kp)
{
    extern __shared__ __align__(16) char hsm[];
    const int tid  = threadIdx.x;
    const int wid  = tid >> 5, lane = tid & 31;
    const int wm   = (wid >> 1) * 64, wn = (wid & 1) * 64;
    const int bm   = blockIdx.y * 256, bn = blockIdx.x * 128;

    auto Arow = [&](int buf, int r) {
        return (__nv_bfloat16*)(hsm + buf * HG_ABUF) + r * 40;
    };
    auto Brow = [&](int buf, int r) {
        return (__nv_bfloat16*)(hsm + HG_B0 + buf * HG_BBUF) + r * 136;
    };

    float acc[4][8][4];
    #pragma unroll
    for (int f = 0; f < 4; f++)
        #pragma unroll
        for (int p = 0; p < 8; p++)
            #pragma unroll
            for (int t = 0; t < 4; t++) acc[f][p][t] = 0.f;

    auto issue_tile = [&](int buf, int k0) {
        #pragma unroll
        for (int t = 0; t < 4; t++) {
            int idx = tid + t * 256;             // 1024 chunks: A 256x32
            int ar = idx >> 2, ac = (idx & 3) * 8;
            cp_async16(Arow(buf, ar) + ac, A + (size_t)(bm + ar) * Kp + k0 + ac);
        }
        #pragma unroll
        for (int t = 0; t < 2; t++) {
            int idx = tid + t * 256;             // 512 chunks: B 32x128
            int br = idx >> 4, bc = (idx & 15) * 8;
            cp_async16(Brow(buf, br) + bc, Bw + (size_t)(k0 + br) * N + bn + bc);
        }
        asm volatile("cp.async.commit_group;\n" ::: "memory");
    };

    const int NIT = Kp / 32;
    issue_tile(0, 0);
    int buf = 0;

    for (int it = 0; it < NIT; it++) {
        if (it + 1 < NIT) {
            issue_tile(buf ^ 1, (it + 1) * 32);
            asm volatile("cp.async.wait_group 1;\n" ::: "memory");
        } else {
            asm volatile("cp.async.wait_group 0;\n" ::: "memory");
        }
        __syncthreads();

        #pragma unroll
        for (int kk = 0; kk < 32; kk += 16) {
            unsigned af[4][4];
            #pragma unroll
            for (int f = 0; f < 4; f++) {
                int row = wm + f * 16 + (lane & 15);
                int col = kk + (lane >> 4) * 8;
                LDSM4(af[f][0], af[f][1], af[f][2], af[f][3], Arow(buf, row) + col);
            }
            unsigned bfr[8][2];
            #pragma unroll
            for (int p = 0; p < 4; p++) {
                int krow = kk + (lane & 7) + ((lane >> 3) & 1) * 8;
                int ncol = wn + p * 16 + (lane >> 4) * 8;
                unsigned r0, r1, r2, r3;
                LDSM4T(r0, r1, r2, r3, Brow(buf, krow) + ncol);
                bfr[p*2][0] = r0; bfr[p*2][1] = r1; bfr[p*2+1][0] = r2; bfr[p*2+1][1] = r3;
            }
            #pragma unroll
            for (int f = 0; f < 4; f++)
                #pragma unroll
                for (int p = 0; p < 8; p++)
                    MMA16816(acc[f][p], af[f][0], af[f][1], af[f][2], af[f][3],
                             bfr[p][0], bfr[p][1]);
        }
        __syncthreads();
        buf ^= 1;
    }

    const int r0 = lane >> 2, c0 = (lane & 3) * 2;
    #pragma unroll
    for (int f = 0; f < 4; f++) {
        #pragma unroll
        for (int p = 0; p < 8; p++) {
            const int grow = bm + wm + f * 16 + r0;
            const int gcol = bn + wn + p * 8 + c0;
            const float b0 = bias[gcol], b1 = bias[gcol + 1];
            float v00 = acc[f][p][0] + b0, v01 = acc[f][p][1] + b1;
            float v10 = acc[f][p][2] + b0, v11 = acc[f][p][3] + b1;
            if (EPI == 1) {
                v00 = 0.5f * v00 * (1.0f + erff(v00 * 0.70710678118654752f));
                v01 = 0.5f * v01 * (1.0f + erff(v01 * 0.70710678118654752f));
                v10 = 0.5f * v10 * (1.0f + erff(v10 * 0.70710678118654752f));
                v11 = 0.5f * v11 * (1.0f + erff(v11 * 0.70710678118654752f));
            }
            float2 lo = {v00, v01}, hi = {v10, v11};
            *(float2*)(C + (size_t)grow * N + gcol)       = lo;
            *(float2*)(C + (size_t)(grow + 8) * N + gcol) = hi;
        }
    }
}

// ================= tensor-core flash attention =================
struct FlashSmem {
    __nv_bfloat16 Q2[128][136];
    __nv_bfloat16 K2[32][136];
    __nv_bfloat16 V2[64][72];
    __nv_bfloat16 P2[128][72];
    float msk[32];
};

__global__ void __launch_bounds__(256) flash_attn_tc_kernel(
    const float* __restrict__ Q, const float* __restrict__ Kx,
    const float* __restrict__ V, const float* __restrict__ mask,
    float* __restrict__ O, int Lq, int Lk, float scale)
{
    extern __shared__ char fsm_raw[];
    FlashSmem* sm = (FlashSmem*)fsm_raw;

    const int bh = blockIdx.y;
    const int b = bh >> 4, h = bh & 15;
    const int q0 = blockIdx.x * 128;
    const int tid = threadIdx.x, wid = tid >> 5, lane = tid & 31;
    const int r0 = lane >> 2;
    const int cc = (lane & 3) * 2;

    #pragma unroll
    for (int it = 0; it < 8; it++) {
        int idx = tid + it * 256;
        int r = idx >> 4, c4 = (idx & 15) * 4;
        float4 qv = *(const float4*)(Q + (size_t)(b*Lq + q0 + r) * D + h*HD + c4);
        float xs[4] = {qv.x, qv.y, qv.z, qv.w};
        unsigned short hu[4], lu[4];
        #pragma unroll
        for (int t = 0; t < 4; t++) {
            __nv_bfloat16 hh = __float2bfloat16(xs[t]);
            __nv_bfloat16 ll = __float2bfloat16(xs[t] - __bfloat162float(hh));
            hu[t] = *(unsigned short*)&hh; lu[t] = *(unsigned short*)&ll;
        }
        ushort4 h4 = {hu[0], hu[1], hu[2], hu[3]};
        ushort4 l4 = {lu[0], lu[1], lu[2], lu[3]};
        *(ushort4*)&sm->Q2[r][c4]      = h4;
        *(ushort4*)&sm->Q2[r][64 + c4] = l4;
    }

    float m0 = -1e30f, m1 = -1e30f, l0 = 0.f, l1 = 0.f;
    float o[8][4];
    #pragma unroll
    for (int d = 0; d < 8; d++)
        #pragma unroll
        for (int t = 0; t < 4; t++) o[d][t] = 0.f;

    for (int k0 = 0; k0 < Lk; k0 += 32) {
        __syncthreads();

        #pragma unroll
        for (int it = 0; it < 2; it++) {
            int idx = tid + it * 256;
            int r = idx >> 4, c4 = (idx & 15) * 4;
            const size_t g = (size_t)(b*Lk + k0 + r) * D + h*HD + c4;
            float4 kv = *(const float4*)(Kx + g);
            float4 vv = *(const float4*)(V + g);
            float ks[4] = {kv.x, kv.y, kv.z, kv.w};
            float vs[4] = {vv.x, vv.y, vv.z, vv.w};
            unsigned short khu[4], klu[4], vhu[4], vlu[4];
            #pragma unroll
            for (int t = 0; t < 4; t++) {
                __nv_bfloat16 hh = __float2bfloat16(ks[t]);
                __nv_bfloat16 ll = __float2bfloat16(ks[t] - __bfloat162float(hh));
                khu[t] = *(unsigned short*)&hh; klu[t] = *(unsigned short*)&ll;
                hh = __float2bfloat16(vs[t]);
                ll = __float2bfloat16(vs[t] - __bfloat162float(hh));
                vhu[t] = *(unsigned short*)&hh; vlu[t] = *(unsigned short*)&ll;
            }
            ushort4 kh4 = {khu[0], khu[1], khu[2], khu[3]};
            ushort4 kl4 = {klu[0], klu[1], klu[2], klu[3]};
            ushort4 vh4 = {vhu[0], vhu[1], vhu[2], vhu[3]};
            ushort4 vl4 = {vlu[0], vlu[1], vlu[2], vlu[3]};
            *(ushort4*)&sm->K2[r][c4]      = kh4;
            *(ushort4*)&sm->K2[r][64 + c4] = kl4;
            *(ushort4*)&sm->V2[r][c4]      = vh4;
            *(ushort4*)&sm->V2[32 + r][c4] = vl4;
        }
        if (tid < 32) sm->msk[tid] = mask ? mask[(size_t)b * Lk + k0 + tid] : 0.f;
        __syncthreads();

        float sf[4][4];
        #pragma unroll
        for (int nb = 0; nb < 4; nb++)
            #pragma unroll
            for (int t = 0; t < 4; t++) sf[nb][t] = 0.f;

        const int qc[12] = {0,16,32,48, 0,16,32,48, 64,80,96,112};
        const int kc[12] = {0,16,32,48, 64,80,96,112, 0,16,32,48};
        #pragma unroll
        for (int s = 0; s < 12; s++) {
            unsigned af[4];
            LDSM4(af[0], af[1], af[2], af[3],
                  &sm->Q2[wid*16 + (lane & 15)][qc[s] + (lane >> 4) * 8]);
            #pragma unroll
            for (int nb = 0; nb < 2; nb++) {
                unsigned t0, t1, t2, t3;
                LDSM4(t0, t1, t2, t3,
                      &sm->K2[nb*16 + (lane & 15)][kc[s] + (lane >> 4) * 8]);
                MMA16816(sf[nb*2],     af[0], af[1], af[2], af[3], t0, t2);
                MMA16816(sf[nb*2 + 1], af[0], af[1], af[2], af[3], t1, t3);
            }
        }

        #pragma unroll
        for (int nb = 0; nb < 4; nb++) {
            float mv0 = sm->msk[nb*8 + cc], mv1 = sm->msk[nb*8 + cc + 1];
            sf[nb][0] = sf[nb][0] * scale + mv0;
            sf[nb][1] = sf[nb][1] * scale + mv1;
            sf[nb][2] = sf[nb][2] * scale + mv0;
            sf[nb][3] = sf[nb][3] * scale + mv1;
        }

        float tm0 = -1e30f, tm1 = -1e30f;
        #pragma unroll
        for (int nb = 0; nb < 4; nb++) {
            tm0 = fmaxf(tm0, fmaxf(sf[nb][0], sf[nb][1]));
            tm1 = fmaxf(tm1, fmaxf(sf[nb][2], sf[nb][3]));
        }
        tm0 = fmaxf(tm0, __shfl_xor_sync(0xffffffffu, tm0, 1));
        tm0 = fmaxf(tm0, __shfl_xor_sync(0xffffffffu, tm0, 2));
        tm1 = fmaxf(tm1, __shfl_xor_sync(0xffffffffu, tm1, 1));
        tm1 = fmaxf(tm1, __shfl_xor_sync(0xffffffffu, tm1, 2));

        const float nm0 = fmaxf(m0, tm0), nm1 = fmaxf(m1, tm1);
        const float corr0 = __expf(m0 - nm0), corr1 = __expf(m1 - nm1);
        m0 = nm0; m1 = nm1;

        float ts0 = 0.f, ts1 = 0.f;
        #pragma unroll
        for (int nb = 0; nb < 4; nb++) {
            sf[nb][0] = __expf(sf[nb][0] - nm0);
            sf[nb][1] = __expf(sf[nb][1] - nm0);
            sf[nb][2] = __expf(sf[nb][2] - nm1);
            sf[nb][3] = __expf(sf[nb][3] - nm1);
            ts0 += sf[nb][0] + sf[nb][1];
            ts1 += sf[nb][2] + sf[nb][3];
        }
        ts0 += __shfl_xor_sync(0xffffffffu, ts0, 1);
        ts0 += __shfl_xor_sync(0xffffffffu, ts0, 2);
        ts1 += __shfl_xor_sync(0xffffffffu, ts1, 1);
        ts1 += __shfl_xor_sync(0xffffffffu, ts1, 2);
        l0 = l0 * corr0 + ts0;
        l1 = l1 * corr1 + ts1;

        const int pr0 = wid*16 + r0, pr1 = pr0 + 8;
        #pragma unroll
        for (int nb = 0; nb < 4; nb++) {
            #pragma unroll
            for (int half = 0; half < 2; half++) {
                const int prow = half ? pr1 : pr0;
                float p0 = sf[nb][half*2], p1 = sf[nb][half*2 + 1];
                __nv_bfloat16 h0 = __float2bfloat16(p0);
                __nv_bfloat16 h1 = __float2bfloat16(p1);
                __nv_bfloat16 e0 = __float2bfloat16(p0 - __bfloat162float(h0));
                __nv_bfloat16 e1 = __float2bfloat16(p1 - __bfloat162float(h1));
                unsigned ph = (unsigned)*(unsigned short*)&h0 |
                              ((unsigned)*(unsigned short*)&h1 << 16);
                unsigned pl = (unsigned)*(unsigned short*)&e0 |
                              ((unsigned)*(unsigned short*)&e1 << 16);
                *(unsigned*)&sm->P2[prow][nb*8 + cc]      = ph;
                *(unsigned*)&sm->P2[prow][32 + nb*8 + cc] = pl;
            }
        }

        #pragma unroll
        for (int d = 0; d < 8; d++) {
            o[d][0] *= corr0; o[d][1] *= corr0;
            o[d][2] *= corr1; o[d][3] *= corr1;
        }
        __syncthreads();

        const int pc[6] = {0, 16, 32, 48, 0, 16};
        const int vc[6] = {0, 16, 0, 16, 32, 48};
        #pragma unroll
        for (int s = 0; s < 6; s++) {
            unsigned af[4];
            LDSM4(af[0], af[1], af[2], af[3],
                  &sm->P2[wid*16 + (lane & 15)][pc[s] + (lane >> 4) * 8]);
            #pragma unroll
            for (int p = 0; p < 4; p++) {
                unsigned t0, t1, t2, t3;
                int krow = vc[s] + (lane & 7) + ((lane >> 3) & 1) * 8;
                int ncol = p*16 + (lane >> 4) * 8;
                LDSM4T(t0, t1, t2, t3, &sm->V2[krow][ncol]);
                MMA16816(o[p*2],     af[0], af[1], af[2], af[3], t0, t1);
                MMA16816(o[p*2 + 1], af[0], af[1], af[2], af[3], t2, t3);
            }
        }
    }

    const float li0 = 1.f / l0, li1 = 1.f / l1;
    const int gq0 = b*Lq + q0 + wid*16 + r0;
    #pragma unroll
    for (int d = 0; d < 8; d++) {
        float2 v0 = {o[d][0] * li0, o[d][1] * li0};
        float2 v1 = {o[d][2] * li1, o[d][3] * li1};
        *(float2*)(O + (size_t)gq0 * D + h*HD + d*8 + cc)       = v0;
        *(float2*)(O + (size_t)(gq0 + 8) * D + h*HD + d*8 + cc) = v1;
    }
}

// ================= residual + LayerNorm =================
__global__ void __launch_bounds__(256) ln_residual_kernel(
    const float* __restrict__ Y, const float* __restrict__ R,
    const float* __restrict__ g, const float* __restrict__ be,
    float* __restrict__ O)
{
    const size_t row = blockIdx.x;
    const int tid = threadIdx.x;
    const float* y = Y + row * D;
    const float* r = R + row * D;
    __shared__ float red[256];

    float h[4];
    float s = 0.f;
    #pragma unroll
    for (int i = 0; i < 4; i++) {
        h[i] = y[tid + i*256] + r[tid + i*256];
        s += h[i];
    }
    red[tid] = s; __syncthreads();
    for (int st = 128; st > 0; st >>= 1) {
        if (tid < st) red[tid] += red[tid + st];
        __syncthreads();
    }
    const float mean = red[0] * (1.0f / D);
    __syncthreads();

    float vs = 0.f;
    #pragma unroll
    for (int i = 0; i < 4; i++) {
        float dd = h[i] - mean;
        vs += dd * dd;
    }
    red[tid] = vs; __syncthreads();
    for (int st = 128; st > 0; st >>= 1) {
        if (tid < st) red[tid] += red[tid + st];
        __syncthreads();
    }
    const float inv = rsqrtf(red[0] * (1.0f / D) + 1e-5f);

    #pragma unroll
    for (int i = 0; i < 4; i++) {
        const int c = tid + i*256;
        O[row * D + c] = (h[i] - mean) * inv * g[c] + be[c];
    }
}

// ================= host launch =================
extern "C" void kernel_launch(void* const* d_in, const int* in_sizes, int n_in,
                              void* d_out, int out_size)
{
    const float* input = (const float*)d_in[0];
    const float* ctx   = (const float*)d_in[1];
    const float* mask  = (const float*)d_in[2];
    const float* cq_w = (const float*)d_in[3];  const float* cq_b = (const float*)d_in[4];
    const float* ck_w = (const float*)d_in[5];  const float* ck_b = (const float*)d_in[6];
    const float* cv_w = (const float*)d_in[7];  const float* cv_b = (const float*)d_in[8];
    const float* co_w = (const float*)d_in[9];  const float* co_b = (const float*)d_in[10];
    const float* co_g = (const float*)d_in[11]; const float* co_be= (const float*)d_in[12];
    const float* sq_w = (const float*)d_in[13]; const float* sq_b = (const float*)d_in[14];
    const float* sk_w = (const float*)d_in[15]; const float* sk_b = (const float*)d_in[16];
    const float* sv_w = (const float*)d_in[17]; const float* sv_b = (const float*)d_in[18];
    const float* so_w = (const float*)d_in[19]; const float* so_b = (const float*)d_in[20];
    const float* so_g = (const float*)d_in[21]; const float* so_be= (const float*)d_in[22];
    const float* fi_w = (const float*)d_in[23]; const float* fi_b = (const float*)d_in[24];
    const float* fo_w = (const float*)d_in[25]; const float* fo_b = (const float*)d_in[26];
    const float* fo_g = (const float*)d_in[27]; const float* fo_be= (const float*)d_in[28];

    float *q, *k, *v, *att, *x, *x2, *y, *inter;
    __nv_bfloat16 *sa, *sb;
    cudaGetSymbolAddress((void**)&q,    g_q);
    cudaGetSymbolAddress((void**)&k,    g_k);
    cudaGetSymbolAddress((void**)&v,    g_v);
    cudaGetSymbolAddress((void**)&att,  g_att);
    cudaGetSymbolAddress((void**)&x,    g_x);
    cudaGetSymbolAddress((void**)&x2,   g_x2);
    cudaGetSymbolAddress((void**)&y,    g_y);
    cudaGetSymbolAddress((void**)&inter,g_int);
    cudaGetSymbolAddress((void**)&sa,   g_sa);
    cudaGetSymbolAddress((void**)&sb,   g_sb);

    const float scale = 0.125f; // 1/sqrt(64)
    dim3 blk(256);
    const int FLASH_SMEM = (int)sizeof(FlashSmem);
    static int smem_set = 0;
    if (!smem_set) {
        cudaFuncSetAttribute(flash_attn_tc_kernel,
                             cudaFuncAttributeMaxDynamicSharedMemorySize, FLASH_SMEM);
        cudaFuncSetAttribute(hgemm_kernel<0>,
                             cudaFuncAttributeMaxDynamicSharedMemorySize, HG_SMEM);
        cudaFuncSetAttribute(hgemm_kernel<1>,
                             cudaFuncAttributeMaxDynamicSharedMemorySize, HG_SMEM);
        smem_set = 1;
    }

    #define SPLIT_A(X, R, C, SH)  split_a_kernel<<<((size_t)(R)*(C))/1024, blk>>>((X), sa, (C)-1, (SH))
    #define SPLIT_B(W, K_, N_, SH) split_b_kernel<<<((size_t)(K_)*(N_))/1024, blk>>>((W), sb, (K_), (N_)-1, (SH))
    #define GEMM(EPI, BIAS, OUT, M_, N_, K3) \
        hgemm_kernel<EPI><<<dim3((N_)/128, (M_)/256), blk, HG_SMEM>>>(sa, sb, (BIAS), (OUT), (N_), (K3))

    // ---- cross attention ----
    SPLIT_A(input, MQ, D, 10);
    SPLIT_B(cq_w, D, D, 10);  GEMM(0, cq_b, q, MQ, D, 3*D);
    SPLIT_A(ctx, MCTX, D, 10);
    SPLIT_B(ck_w, D, D, 10);  GEMM(0, ck_b, k, MCTX, D, 3*D);
    SPLIT_B(cv_w, D, D, 10);  GEMM(0, cv_b, v, MCTX, D, 3*D);

    flash_attn_tc_kernel<<<dim3(LQ/128, B*H), blk, FLASH_SMEM>>>(q, k, v, mask, att, LQ, LK, scale);

    SPLIT_A(att, MQ, D, 10);
    SPLIT_B(co_w, D, D, 10);  GEMM(0, co_b, y, MQ, D, 3*D);
    ln_residual_kernel<<<MQ, blk>>>(y, input, co_g, co_be, x);

    // ---- self attention ----
    SPLIT_A(x, MQ, D, 10);
    SPLIT_B(sq_w, D, D, 10);  GEMM(0, sq_b, q, MQ, D, 3*D);
    SPLIT_B(sk_w, D, D, 10);  GEMM(0, sk_b, k, MQ, D, 3*D);
    SPLIT_B(sv_w, D, D, 10);  GEMM(0, sv_b, v, MQ, D, 3*D);

    flash_attn_tc_kernel<<<dim3(LQ/128, B*H), blk, FLASH_SMEM>>>(q, k, v, nullptr, att, LQ, LQ, scale);

    SPLIT_A(att, MQ, D, 10);
    SPLIT_B(so_w, D, D, 10);  GEMM(0, so_b, y, MQ, D, 3*D);
    ln_residual_kernel<<<MQ, blk>>>(y, x, so_g, so_be, x2);

    // ---- FFN ----
    SPLIT_A(x2, MQ, D, 10);
    SPLIT_B(fi_w, D, F, 12);  GEMM(1, fi_b, inter, MQ, F, 3*D);
    SPLIT_A(inter, MQ, F, 12);
    SPLIT_B(fo_w, F, D, 10);  GEMM(0, fo_b, y, MQ, D, 3*F);
    ln_residual_kernel<<<MQ, blk>>>(y, x2, fo_g, fo_be, (float*)d_out);

    #undef SPLIT_A
    #undef SPLIT_B
    #undef GEMM
}

// round 13
// speedup vs baseline: 1.6402x; 1.6402x over previous
#include <cuda_runtime.h>
#include <cuda_bf16.h>
#include <cstdint>
#include <stdint.h>
#include <math.h>

// ---------------- problem constants ----------------
#define B    4
#define LQ   1024
#define LK   2048
#define D    1024
#define H    16
#define HD   64
#define F    4096
#define MQ   (B*LQ)     // 4096
#define MCTX (B*LK)     // 8192

// ---------------- scratch (static __device__, no allocs) ----------------
__device__ float g_q   [(size_t)MQ   * D];
__device__ float g_k   [(size_t)MCTX * D];
__device__ float g_v   [(size_t)MCTX * D];
__device__ float g_att [(size_t)MQ * D];
__device__ float g_x   [(size_t)MQ * D];
__device__ float g_x2  [(size_t)MQ * D];
__device__ float g_y   [(size_t)MQ * D];
__device__ float g_int [(size_t)MQ * F];
__device__ __nv_bfloat16 g_sa [(size_t)MQ * 3 * F];      // A' split buffer
__device__ __nv_bfloat16 g_sb [(size_t)3 * F * D];       // B' split buffer

// ---------------- asm helpers ----------------
__device__ __forceinline__ unsigned smem_u32(const void* p) {
    return (unsigned)__cvta_generic_to_shared(p);
}

#define LDSM4(R0,R1,R2,R3,PTR) do { \
    unsigned _a = smem_u32(PTR); \
    asm volatile("ldmatrix.sync.aligned.m8n8.x4.shared.b16 {%0,%1,%2,%3}, [%4];" \
        : "=r"(R0),"=r"(R1),"=r"(R2),"=r"(R3) : "r"(_a)); } while(0)

#define LDSM4T(R0,R1,R2,R3,PTR) do { \
    unsigned _a = smem_u32(PTR); \
    asm volatile("ldmatrix.sync.aligned.m8n8.x4.trans.shared.b16 {%0,%1,%2,%3}, [%4];" \
        : "=r"(R0),"=r"(R1),"=r"(R2),"=r"(R3) : "r"(_a)); } while(0)

#define MMA16816(C,A0,A1,A2,A3,B0,B1) \
    asm volatile("mma.sync.aligned.m16n8k16.row.col.f32.bf16.bf16.f32 " \
        "{%0,%1,%2,%3},{%4,%5,%6,%7},{%8,%9},{%0,%1,%2,%3};" \
        : "+f"((C)[0]), "+f"((C)[1]), "+f"((C)[2]), "+f"((C)[3]) \
        : "r"(A0), "r"(A1), "r"(A2), "r"(A3), "r"(B0), "r"(B1))

__device__ __forceinline__ void cp_async16(void* smem, const void* gmem) {
    unsigned s = smem_u32(smem);
    asm volatile("cp.async.cg.shared.global [%0], [%1], 16;\n" :: "r"(s), "l"(gmem));
}

// ================= bf16 split conversion (GEMM operands) =================
__global__ void __launch_bounds__(256) split_a_kernel(
    const float* __restrict__ X, __nv_bfloat16* __restrict__ Y, int cmask, int cshift)
{
    const size_t i4 = ((size_t)blockIdx.x * 256 + threadIdx.x) * 4;
    const int C = cmask + 1;
    const size_t r = i4 >> cshift;
    const int c = (int)(i4 & cmask);
    float4 x = *(const float4*)(X + i4);
    float xs[4] = {x.x, x.y, x.z, x.w};
    unsigned short hu[4], lu[4];
    #pragma unroll
    for (int t = 0; t < 4; t++) {
        __nv_bfloat16 hh = __float2bfloat16(xs[t]);
        __nv_bfloat16 ll = __float2bfloat16(xs[t] - __bfloat162float(hh));
        hu[t] = *(unsigned short*)&hh; lu[t] = *(unsigned short*)&ll;
    }
    ushort4 h4 = {hu[0], hu[1], hu[2], hu[3]};
    ushort4 l4 = {lu[0], lu[1], lu[2], lu[3]};
    __nv_bfloat16* row = Y + r * (size_t)(3 * C);
    *(ushort4*)(row + c)         = h4;
    *(ushort4*)(row + C + c)     = h4;
    *(ushort4*)(row + 2 * C + c) = l4;
}

__global__ void __launch_bounds__(256) split_b_kernel(
    const float* __restrict__ W, __nv_bfloat16* __restrict__ Y, int K, int nmask, int nshift)
{
    const size_t i4 = ((size_t)blockIdx.x * 256 + threadIdx.x) * 4;
    const int N = nmask + 1;
    const size_t r = i4 >> nshift;
    const int c = (int)(i4 & nmask);
    float4 x = *(const float4*)(W + i4);
    float xs[4] = {x.x, x.y, x.z, x.w};
    unsigned short hu[4], lu[4];
    #pragma unroll
    for (int t = 0; t < 4; t++) {
        __nv_bfloat16 hh = __float2bfloat16(xs[t]);
        __nv_bfloat16 ll = __float2bfloat16(xs[t] - __bfloat162float(hh));
        hu[t] = *(unsigned short*)&hh; lu[t] = *(unsigned short*)&ll;
    }
    ushort4 h4 = {hu[0], hu[1], hu[2], hu[3]};
    ushort4 l4 = {lu[0], lu[1], lu[2], lu[3]};
    *(ushort4*)(Y + r * (size_t)N + c)             = h4;  // Bh
    *(ushort4*)(Y + ((size_t)K + r) * N + c)       = l4;  // Bl
    *(ushort4*)(Y + ((size_t)(2 * K) + r) * N + c) = h4;  // Bh
}

// ================= bf16 tensor-core GEMM (BM=128, BN=128, BK=32, 4-stage) ==========
// 8 warps as 4x2; warp tile 32x64 (f=2 m16 frags x p=8 n8 frags). Round-9 shape.
#define HG_ABUF (128 * 40 * 2)              // 10240 B per stage
#define HG_BBUF (32 * 136 * 2)              // 8704 B per stage
#define HG_STAGE (HG_ABUF + HG_BBUF)        // 18944 B
#define HG_SMEM (4 * HG_STAGE)              // 75776 B

template<int EPI>  // 0 = bias, 1 = bias + exact gelu
__global__ void __launch_bounds__(256) hgemm_kernel(
    const __nv_bfloat16* __restrict__ A, const __nv_bfloat16* __restrict__ Bw,
    const float* __restrict__ bias, float* __restrict__ C,
    int N, int Kp)
{
    extern __shared__ __align__(16) char hsm[];
    const int tid  = threadIdx.x;
    const int wid  = tid >> 5, lane = tid & 31;
    const int wm   = (wid >> 1) * 32, wn = (wid & 1) * 64;
    const int bm   = blockIdx.y * 128, bn = blockIdx.x * 128;

    auto Arow = [&](int buf, int r) {
        return (__nv_bfloat16*)(hsm + buf * HG_STAGE) + r * 40;
    };
    auto Brow = [&](int buf, int r) {
        return (__nv_bfloat16*)(hsm + buf * HG_STAGE + HG_ABUF) + r * 136;
    };

    float acc[2][8][4];
    #pragma unroll
    for (int f = 0; f < 2; f++)
        #pragma unroll
        for (int p = 0; p < 8; p++)
            #pragma unroll
            for (int t = 0; t < 4; t++) acc[f][p][t] = 0.f;

    auto issue_tile = [&](int buf, int k0) {
        #pragma unroll
        for (int t = 0; t < 2; t++) {
            int idx = tid + t * 256;                 // 512 chunks: A 128x32
            int ar = idx >> 2, ac = (idx & 3) * 8;
            cp_async16(Arow(buf, ar) + ac, A + (size_t)(bm + ar) * Kp + k0 + ac);
        }
        #pragma unroll
        for (int t = 0; t < 2; t++) {
            int idx = tid + t * 256;                 // 512 chunks: B 32x128
            int br = idx >> 4, bc = (idx & 15) * 8;
            cp_async16(Brow(buf, br) + bc, Bw + (size_t)(k0 + br) * N + bn + bc);
        }
        asm volatile("cp.async.commit_group;\n" ::: "memory");
    };

    const int NIT = Kp / 32;
    issue_tile(0, 0);
    issue_tile(1, 32);
    issue_tile(2, 64);

    for (int it = 0; it < NIT; it++) {
        if (it + 3 < NIT) {
            issue_tile((it + 3) & 3, (it + 3) * 32);
            asm volatile("cp.async.wait_group 3;\n" ::: "memory");
        } else if (it + 2 < NIT) {
            asm volatile("cp.async.wait_group 2;\n" ::: "memory");
        } else if (it + 1 < NIT) {
            asm volatile("cp.async.wait_group 1;\n" ::: "memory");
        } else {
            asm volatile("cp.async.wait_group 0;\n" ::: "memory");
        }
        __syncthreads();

        const int buf = it & 3;
        #pragma unroll
        for (int kk = 0; kk < 32; kk += 16) {
            unsigned af[2][4];
            #pragma unroll
            for (int f = 0; f < 2; f++) {
                int row = wm + f * 16 + (lane & 15);
                int col = kk + (lane >> 4) * 8;
                LDSM4(af[f][0], af[f][1], af[f][2], af[f][3], Arow(buf, row) + col);
            }
            unsigned bfr[8][2];
            #pragma unroll
            for (int p = 0; p < 4; p++) {
                int krow = kk + (lane & 7) + ((lane >> 3) & 1) * 8;
                int ncol = wn + p * 16 + (lane >> 4) * 8;
                unsigned r0, r1, r2, r3;
                LDSM4T(r0, r1, r2, r3, Brow(buf, krow) + ncol);
                bfr[p*2][0] = r0; bfr[p*2][1] = r1; bfr[p*2+1][0] = r2; bfr[p*2+1][1] = r3;
            }
            #pragma unroll
            for (int f = 0; f < 2; f++)
                #pragma unroll
                for (int p = 0; p < 8; p++)
                    MMA16816(acc[f][p], af[f][0], af[f][1], af[f][2], af[f][3],
                             bfr[p][0], bfr[p][1]);
        }
        __syncthreads();
    }

    const int r0 = lane >> 2, c0 = (lane & 3) * 2;
    #pragma unroll
    for (int f = 0; f < 2; f++) {
        #pragma unroll
        for (int p = 0; p < 8; p++) {
            const int grow = bm + wm + f * 16 + r0;
            const int gcol = bn + wn + p * 8 + c0;
            const float b0 = bias[gcol], b1 = bias[gcol + 1];
            float v00 = acc[f][p][0] + b0, v01 = acc[f][p][1] + b1;
            float v10 = acc[f][p][2] + b0, v11 = acc[f][p][3] + b1;
            if (EPI == 1) {
                v00 = 0.5f * v00 * (1.0f + erff(v00 * 0.70710678118654752f));
                v01 = 0.5f * v01 * (1.0f + erff(v01 * 0.70710678118654752f));
                v10 = 0.5f * v10 * (1.0f + erff(v10 * 0.70710678118654752f));
                v11 = 0.5f * v11 * (1.0f + erff(v11 * 0.70710678118654752f));
            }
            float2 lo = {v00, v01}, hi = {v10, v11};
            *(float2*)(C + (size_t)grow * N + gcol)       = lo;
            *(float2*)(C + (size_t)(grow + 8) * N + gcol) = hi;
        }
    }
}

// ================= tensor-core flash attention =================
struct FlashSmem {
    __nv_bfloat16 Q2[128][136];
    __nv_bfloat16 K2[32][136];
    __nv_bfloat16 V2[64][72];
    __nv_bfloat16 P2[128][72];
    float msk[32];
};

__global__ void __launch_bounds__(256) flash_attn_tc_kernel(
    const float* __restrict__ Q, const float* __restrict__ Kx,
    const float* __restrict__ V, const float* __restrict__ mask,
    float* __restrict__ O, int Lq, int Lk, float scale)
{
    extern __shared__ char fsm_raw[];
    FlashSmem* sm = (FlashSmem*)fsm_raw;

    const int bh = blockIdx.y;
    const int b = bh >> 4, h = bh & 15;
    const int q0 = blockIdx.x * 128;
    const int tid = threadIdx.x, wid = tid >> 5, lane = tid & 31;
    const int r0 = lane >> 2;
    const int cc = (lane & 3) * 2;

    #pragma unroll
    for (int it = 0; it < 8; it++) {
        int idx = tid + it * 256;
        int r = idx >> 4, c4 = (idx & 15) * 4;
        float4 qv = *(const float4*)(Q + (size_t)(b*Lq + q0 + r) * D + h*HD + c4);
        float xs[4] = {qv.x, qv.y, qv.z, qv.w};
        unsigned short hu[4], lu[4];
        #pragma unroll
        for (int t = 0; t < 4; t++) {
            __nv_bfloat16 hh = __float2bfloat16(xs[t]);
            __nv_bfloat16 ll = __float2bfloat16(xs[t] - __bfloat162float(hh));
            hu[t] = *(unsigned short*)&hh; lu[t] = *(unsigned short*)&ll;
        }
        ushort4 h4 = {hu[0], hu[1], hu[2], hu[3]};
        ushort4 l4 = {lu[0], lu[1], lu[2], lu[3]};
        *(ushort4*)&sm->Q2[r][c4]      = h4;
        *(ushort4*)&sm->Q2[r][64 + c4] = l4;
    }

    float m0 = -1e30f, m1 = -1e30f, l0 = 0.f, l1 = 0.f;
    float o[8][4];
    #pragma unroll
    for (int d = 0; d < 8; d++)
        #pragma unroll
        for (int t = 0; t < 4; t++) o[d][t] = 0.f;

    for (int k0 = 0; k0 < Lk; k0 += 32) {
        __syncthreads();

        #pragma unroll
        for (int it = 0; it < 2; it++) {
            int idx = tid + it * 256;
            int r = idx >> 4, c4 = (idx & 15) * 4;
            const size_t g = (size_t)(b*Lk + k0 + r) * D + h*HD + c4;
            float4 kv = *(const float4*)(Kx + g);
            float4 vv = *(const float4*)(V + g);
            float ks[4] = {kv.x, kv.y, kv.z, kv.w};
            float vs[4] = {vv.x, vv.y, vv.z, vv.w};
            unsigned short khu[4], klu[4], vhu[4], vlu[4];
            #pragma unroll
            for (int t = 0; t < 4; t++) {
                __nv_bfloat16 hh = __float2bfloat16(ks[t]);
                __nv_bfloat16 ll = __float2bfloat16(ks[t] - __bfloat162float(hh));
                khu[t] = *(unsigned short*)&hh; klu[t] = *(unsigned short*)&ll;
                hh = __float2bfloat16(vs[t]);
                ll = __float2bfloat16(vs[t] - __bfloat162float(hh));
                vhu[t] = *(unsigned short*)&hh; vlu[t] = *(unsigned short*)&ll;
            }
            ushort4 kh4 = {khu[0], khu[1], khu[2], khu[3]};
            ushort4 kl4 = {klu[0], klu[1], klu[2], klu[3]};
            ushort4 vh4 = {vhu[0], vhu[1], vhu[2], vhu[3]};
            ushort4 vl4 = {vlu[0], vlu[1], vlu[2], vlu[3]};
            *(ushort4*)&sm->K2[r][c4]      = kh4;
            *(ushort4*)&sm->K2[r][64 + c4] = kl4;
            *(ushort4*)&sm->V2[r][c4]      = vh4;
            *(ushort4*)&sm->V2[32 + r][c4] = vl4;
        }
        if (tid < 32) sm->msk[tid] = mask ? mask[(size_t)b * Lk + k0 + tid] : 0.f;
        __syncthreads();

        float sf[4][4];
        #pragma unroll
        for (int nb = 0; nb < 4; nb++)
            #pragma unroll
            for (int t = 0; t < 4; t++) sf[nb][t] = 0.f;

        const int qc[12] = {0,16,32,48, 0,16,32,48, 64,80,96,112};
        const int kc[12] = {0,16,32,48, 64,80,96,112, 0,16,32,48};
        #pragma unroll
        for (int s = 0; s < 12; s++) {
            unsigned af[4];
            LDSM4(af[0], af[1], af[2], af[3],
                  &sm->Q2[wid*16 + (lane & 15)][qc[s] + (lane >> 4) * 8]);
            #pragma unroll
            for (int nb = 0; nb < 2; nb++) {
                unsigned t0, t1, t2, t3;
                LDSM4(t0, t1, t2, t3,
                      &sm->K2[nb*16 + (lane & 15)][kc[s] + (lane >> 4) * 8]);
                MMA16816(sf[nb*2],     af[0], af[1], af[2], af[3], t0, t2);
                MMA16816(sf[nb*2 + 1], af[0], af[1], af[2], af[3], t1, t3);
            }
        }

        #pragma unroll
        for (int nb = 0; nb < 4; nb++) {
            float mv0 = sm->msk[nb*8 + cc], mv1 = sm->msk[nb*8 + cc + 1];
            sf[nb][0] = sf[nb][0] * scale + mv0;
            sf[nb][1] = sf[nb][1] * scale + mv1;
            sf[nb][2] = sf[nb][2] * scale + mv0;
            sf[nb][3] = sf[nb][3] * scale + mv1;
        }

        float tm0 = -1e30f, tm1 = -1e30f;
        #pragma unroll
        for (int nb = 0; nb < 4; nb++) {
            tm0 = fmaxf(tm0, fmaxf(sf[nb][0], sf[nb][1]));
            tm1 = fmaxf(tm1, fmaxf(sf[nb][2], sf[nb][3]));
        }
        tm0 = fmaxf(tm0, __shfl_xor_sync(0xffffffffu, tm0, 1));
        tm0 = fmaxf(tm0, __shfl_xor_sync(0xffffffffu, tm0, 2));
        tm1 = fmaxf(tm1, __shfl_xor_sync(0xffffffffu, tm1, 1));
        tm1 = fmaxf(tm1, __shfl_xor_sync(0xffffffffu, tm1, 2));

        const float nm0 = fmaxf(m0, tm0), nm1 = fmaxf(m1, tm1);
        const float corr0 = __expf(m0 - nm0), corr1 = __expf(m1 - nm1);
        m0 = nm0; m1 = nm1;

        float ts0 = 0.f, ts1 = 0.f;
        #pragma unroll
        for (int nb = 0; nb < 4; nb++) {
            sf[nb][0] = __expf(sf[nb][0] - nm0);
            sf[nb][1] = __expf(sf[nb][1] - nm0);
            sf[nb][2] = __expf(sf[nb][2] - nm1);
            sf[nb][3] = __expf(sf[nb][3] - nm1);
            ts0 += sf[nb][0] + sf[nb][1];
            ts1 += sf[nb][2] + sf[nb][3];
        }
        ts0 += __shfl_xor_sync(0xffffffffu, ts0, 1);
        ts0 += __shfl_xor_sync(0xffffffffu, ts0, 2);
        ts1 += __shfl_xor_sync(0xffffffffu, ts1, 1);
        ts1 += __shfl_xor_sync(0xffffffffu, ts1, 2);
        l0 = l0 * corr0 + ts0;
        l1 = l1 * corr1 + ts1;

        const int pr0 = wid*16 + r0, pr1 = pr0 + 8;
        #pragma unroll
        for (int nb = 0; nb < 4; nb++) {
            #pragma unroll
            for (int half = 0; half < 2; half++) {
                const int prow = half ? pr1 : pr0;
                float p0 = sf[nb][half*2], p1 = sf[nb][half*2 + 1];
                __nv_bfloat16 h0 = __float2bfloat16(p0);
                __nv_bfloat16 h1 = __float2bfloat16(p1);
                __nv_bfloat16 e0 = __float2bfloat16(p0 - __bfloat162float(h0));
                __nv_bfloat16 e1 = __float2bfloat16(p1 - __bfloat162float(h1));
                unsigned ph = (unsigned)*(unsigned short*)&h0 |
                              ((unsigned)*(unsigned short*)&h1 << 16);
                unsigned pl = (unsigned)*(unsigned short*)&e0 |
                              ((unsigned)*(unsigned short*)&e1 << 16);
                *(unsigned*)&sm->P2[prow][nb*8 + cc]      = ph;
                *(unsigned*)&sm->P2[prow][32 + nb*8 + cc] = pl;
            }
        }

        #pragma unroll
        for (int d = 0; d < 8; d++) {
            o[d][0] *= corr0; o[d][1] *= corr0;
            o[d][2] *= corr1; o[d][3] *= corr1;
        }
        __syncthreads();

        const int pc[6] = {0, 16, 32, 48, 0, 16};
        const int vc[6] = {0, 16, 0, 16, 32, 48};
        #pragma unroll
        for (int s = 0; s < 6; s++) {
            unsigned af[4];
            LDSM4(af[0], af[1], af[2], af[3],
                  &sm->P2[wid*16 + (lane & 15)][pc[s] + (lane >> 4) * 8]);
            #pragma unroll
            for (int p = 0; p < 4; p++) {
                unsigned t0, t1, t2, t3;
                int krow = vc[s] + (lane & 7) + ((lane >> 3) & 1) * 8;
                int ncol = p*16 + (lane >> 4) * 8;
                LDSM4T(t0, t1, t2, t3, &sm->V2[krow][ncol]);
                MMA16816(o[p*2],     af[0], af[1], af[2], af[3], t0, t1);
                MMA16816(o[p*2 + 1], af[0], af[1], af[2], af[3], t2, t3);
            }
        }
    }

    const float li0 = 1.f / l0, li1 = 1.f / l1;
    const int gq0 = b*Lq + q0 + wid*16 + r0;
    #pragma unroll
    for (int d = 0; d < 8; d++) {
        float2 v0 = {o[d][0] * li0, o[d][1] * li0};
        float2 v1 = {o[d][2] * li1, o[d][3] * li1};
        *(float2*)(O + (size_t)gq0 * D + h*HD + d*8 + cc)       = v0;
        *(float2*)(O + (size_t)(gq0 + 8) * D + h*HD + d*8 + cc) = v1;
    }
}

// ================= residual + LayerNorm =================
__global__ void __launch_bounds__(256) ln_residual_kernel(
    const float* __restrict__ Y, const float* __restrict__ R,
    const float* __restrict__ g, const float* __restrict__ be,
    float* __restrict__ O)
{
    const size_t row = blockIdx.x;
    const int tid = threadIdx.x;
    const float* y = Y + row * D;
    const float* r = R + row * D;
    __shared__ float red[256];

    float h[4];
    float s = 0.f;
    #pragma unroll
    for (int i = 0; i < 4; i++) {
        h[i] = y[tid + i*256] + r[tid + i*256];
        s += h[i];
    }
    red[tid] = s; __syncthreads();
    for (int st = 128; st > 0; st >>= 1) {
        if (tid < st) red[tid] += red[tid + st];
        __syncthreads();
    }
    const float mean = red[0] * (1.0f / D);
    __syncthreads();

    float vs = 0.f;
    #pragma unroll
    for (int i = 0; i < 4; i++) {
        float dd = h[i] - mean;
        vs += dd * dd;
    }
    red[tid] = vs; __syncthreads();
    for (int st = 128; st > 0; st >>= 1) {
        if (tid < st) red[tid] += red[tid + st];
        __syncthreads();
    }
    const float inv = rsqrtf(red[0] * (1.0f / D) + 1e-5f);

    #pragma unroll
    for (int i = 0; i < 4; i++) {
        const int c = tid + i*256;
        O[row * D + c] = (h[i] - mean) * inv * g[c] + be[c];
    }
}

// ================= host launch =================
extern "C" void kernel_launch(void* const* d_in, const int* in_sizes, int n_in,
                              void* d_out, int out_size)
{
    const float* input = (const float*)d_in[0];
    const float* ctx   = (const float*)d_in[1];
    const float* mask  = (const float*)d_in[2];
    const float* cq_w = (const float*)d_in[3];  const float* cq_b = (const float*)d_in[4];
    const float* ck_w = (const float*)d_in[5];  const float* ck_b = (const float*)d_in[6];
    const float* cv_w = (const float*)d_in[7];  const float* cv_b = (const float*)d_in[8];
    const float* co_w = (const float*)d_in[9];  const float* co_b = (const float*)d_in[10];
    const float* co_g = (const float*)d_in[11]; const float* co_be= (const float*)d_in[12];
    const float* sq_w = (const float*)d_in[13]; const float* sq_b = (const float*)d_in[14];
    const float* sk_w = (const float*)d_in[15]; const float* sk_b = (const float*)d_in[16];
    const float* sv_w = (const float*)d_in[17]; const float* sv_b = (const float*)d_in[18];
    const float* so_w = (const float*)d_in[19]; const float* so_b = (const float*)d_in[20];
    const float* so_g = (const float*)d_in[21]; const float* so_be= (const float*)d_in[22];
    const float* fi_w = (const float*)d_in[23]; const float* fi_b = (const float*)d_in[24];
    const float* fo_w = (const float*)d_in[25]; const float* fo_b = (const float*)d_in[26];
    const float* fo_g = (const float*)d_in[27]; const float* fo_be= (const float*)d_in[28];

    float *q, *k, *v, *att, *x, *x2, *y, *inter;
    __nv_bfloat16 *sa, *sb;
    cudaGetSymbolAddress((void**)&q,    g_q);
    cudaGetSymbolAddress((void**)&k,    g_k);
    cudaGetSymbolAddress((void**)&v,    g_v);
    cudaGetSymbolAddress((void**)&att,  g_att);
    cudaGetSymbolAddress((void**)&x,    g_x);
    cudaGetSymbolAddress((void**)&x2,   g_x2);
    cudaGetSymbolAddress((void**)&y,    g_y);
    cudaGetSymbolAddress((void**)&inter,g_int);
    cudaGetSymbolAddress((void**)&sa,   g_sa);
    cudaGetSymbolAddress((void**)&sb,   g_sb);

    const float scale = 0.125f; // 1/sqrt(64)
    dim3 blk(256);
    const int FLASH_SMEM = (int)sizeof(FlashSmem);
    static int smem_set = 0;
    if (!smem_set) {
        cudaFuncSetAttribute(flash_attn_tc_kernel,
                             cudaFuncAttributeMaxDynamicSharedMemorySize, FLASH_SMEM);
        cudaFuncSetAttribute(hgemm_kernel<0>,
                             cudaFuncAttributeMaxDynamicSharedMemorySize, HG_SMEM);
        cudaFuncSetAttribute(hgemm_kernel<1>,
                             cudaFuncAttributeMaxDynamicSharedMemorySize, HG_SMEM);
        smem_set = 1;
    }

    #define SPLIT_A(X, R, C, SH)  split_a_kernel<<<((size_t)(R)*(C))/1024, blk>>>((X), sa, (C)-1, (SH))
    #define SPLIT_B(W, K_, N_, SH) split_b_kernel<<<((size_t)(K_)*(N_))/1024, blk>>>((W), sb, (K_), (N_)-1, (SH))
    #define GEMM(EPI, BIAS, OUT, M_, N_, K3) \
        hgemm_kernel<EPI><<<dim3((N_)/128, (M_)/128), blk, HG_SMEM>>>(sa, sb, (BIAS), (OUT), (N_), (K3))

    // ---- cross attention ----
    SPLIT_A(input, MQ, D, 10);
    SPLIT_B(cq_w, D, D, 10);  GEMM(0, cq_b, q, MQ, D, 3*D);
    SPLIT_A(ctx, MCTX, D, 10);
    SPLIT_B(ck_w, D, D, 10);  GEMM(0, ck_b, k, MCTX, D, 3*D);
    SPLIT_B(cv_w, D, D, 10);  GEMM(0, cv_b, v, MCTX, D, 3*D);

    flash_attn_tc_kernel<<<dim3(LQ/128, B*H), blk, FLASH_SMEM>>>(q, k, v, mask, att, LQ, LK, scale);

    SPLIT_A(att, MQ, D, 10);
    SPLIT_B(co_w, D, D, 10);  GEMM(0, co_b, y, MQ, D, 3*D);
    ln_residual_kernel<<<MQ, blk>>>(y, input, co_g, co_be, x);

    // ---- self attention ----
    SPLIT_A(x, MQ, D, 10);
    SPLIT_B(sq_w, D, D, 10);  GEMM(0, sq_b, q, MQ, D, 3*D);
    SPLIT_B(sk_w, D, D, 10);  GEMM(0, sk_b, k, MQ, D, 3*D);
    SPLIT_B(sv_w, D, D, 10);  GEMM(0, sv_b, v, MQ, D, 3*D);

    flash_attn_tc_kernel<<<dim3(LQ/128, B*H), blk, FLASH_SMEM>>>(q, k, v, nullptr, att, LQ, LQ, scale);

    SPLIT_A(att, MQ, D, 10);
    SPLIT_B(so_w, D, D, 10);  GEMM(0, so_b, y, MQ, D, 3*D);
    ln_residual_kernel<<<MQ, blk>>>(y, x, so_g, so_be, x2);

    // ---- FFN ----
    SPLIT_A(x2, MQ, D, 10);
    SPLIT_B(fi_w, D, F, 12);  GEMM(1, fi_b, inter, MQ, F, 3*D);
    SPLIT_A(inter, MQ, F, 12);
    SPLIT_B(fo_w, F, D, 10);  GEMM(0, fo_b, y, MQ, D, 3*F);
    ln_residual_kernel<<<MQ, blk>>>(y, x2, fo_g, fo_be, (float*)d_out);

    #undef SPLIT_A
    #undef SPLIT_B
    #undef GEMM
}

// round 15
// speedup vs baseline: 1.7529x; 1.0687x over previous
#include <cuda_runtime.h>
#include <cuda_bf16.h>
#include <cstdint>
#include <stdint.h>
#include <math.h>

// ---------------- problem constants ----------------
#define B    4
#define LQ   1024
#define LK   2048
#define D    1024
#define H    16
#define HD   64
#define F    4096
#define MQ   (B*LQ)     // 4096
#define MCTX (B*LK)     // 8192

// ---------------- scratch (static __device__, no allocs) ----------------
__device__ float g_q   [(size_t)MQ   * D];
__device__ float g_k   [(size_t)MCTX * D];
__device__ float g_v   [(size_t)MCTX * D];
__device__ float g_x   [(size_t)MQ * D];
__device__ float g_x2  [(size_t)MQ * D];
__device__ float g_y   [(size_t)MQ * D];
__device__ __nv_bfloat16 g_sa  [(size_t)MQ * 3 * F];     // inter split (fi -> fo)
__device__ __nv_bfloat16 g_sa2 [(size_t)MCTX * 3 * D];   // all D-wide A splits
__device__ __nv_bfloat16 g_sb  [(size_t)3 * F * D];      // B' split buffer

// ---------------- asm helpers ----------------
__device__ __forceinline__ unsigned smem_u32(const void* p) {
    return (unsigned)__cvta_generic_to_shared(p);
}

#define LDSM4(R0,R1,R2,R3,PTR) do { \
    unsigned _a = smem_u32(PTR); \
    asm volatile("ldmatrix.sync.aligned.m8n8.x4.shared.b16 {%0,%1,%2,%3}, [%4];" \
        : "=r"(R0),"=r"(R1),"=r"(R2),"=r"(R3) : "r"(_a)); } while(0)

#define LDSM4T(R0,R1,R2,R3,PTR) do { \
    unsigned _a = smem_u32(PTR); \
    asm volatile("ldmatrix.sync.aligned.m8n8.x4.trans.shared.b16 {%0,%1,%2,%3}, [%4];" \
        : "=r"(R0),"=r"(R1),"=r"(R2),"=r"(R3) : "r"(_a)); } while(0)

#define MMA16816(C,A0,A1,A2,A3,B0,B1) \
    asm volatile("mma.sync.aligned.m16n8k16.row.col.f32.bf16.bf16.f32 " \
        "{%0,%1,%2,%3},{%4,%5,%6,%7},{%8,%9},{%0,%1,%2,%3};" \
        : "+f"((C)[0]), "+f"((C)[1]), "+f"((C)[2]), "+f"((C)[3]) \
        : "r"(A0), "r"(A1), "r"(A2), "r"(A3), "r"(B0), "r"(B1))

__device__ __forceinline__ void cp_async16(void* smem, const void* gmem) {
    unsigned s = smem_u32(smem);
    asm volatile("cp.async.cg.shared.global [%0], [%1], 16;\n" :: "r"(s), "l"(gmem));
}

// emit split pair (2 consecutive cols) to a split row: [h,h,l] at col, C+col, 2C+col
__device__ __forceinline__ void emit_split_pair(
    __nv_bfloat16* row, int C, int col, float a, float b)
{
    __nv_bfloat16 h0 = __float2bfloat16(a), h1 = __float2bfloat16(b);
    __nv_bfloat16 l0 = __float2bfloat16(a - __bfloat162float(h0));
    __nv_bfloat16 l1 = __float2bfloat16(b - __bfloat162float(h1));
    unsigned hp = (unsigned)*(unsigned short*)&h0 | ((unsigned)*(unsigned short*)&h1 << 16);
    unsigned lp = (unsigned)*(unsigned short*)&l0 | ((unsigned)*(unsigned short*)&l1 << 16);
    *(unsigned*)(row + col)         = hp;
    *(unsigned*)(row + C + col)     = hp;
    *(unsigned*)(row + 2 * C + col) = lp;
}

// ================= bf16 split conversion (external inputs only) =================
__global__ void __launch_bounds__(256) split_a_kernel(
    const float* __restrict__ X, __nv_bfloat16* __restrict__ Y, int cmask, int cshift)
{
    const size_t i4 = ((size_t)blockIdx.x * 256 + threadIdx.x) * 4;
    const int C = cmask + 1;
    const size_t r = i4 >> cshift;
    const int c = (int)(i4 & cmask);
    float4 x = *(const float4*)(X + i4);
    float xs[4] = {x.x, x.y, x.z, x.w};
    unsigned short hu[4], lu[4];
    #pragma unroll
    for (int t = 0; t < 4; t++) {
        __nv_bfloat16 hh = __float2bfloat16(xs[t]);
        __nv_bfloat16 ll = __float2bfloat16(xs[t] - __bfloat162float(hh));
        hu[t] = *(unsigned short*)&hh; lu[t] = *(unsigned short*)&ll;
    }
    ushort4 h4 = {hu[0], hu[1], hu[2], hu[3]};
    ushort4 l4 = {lu[0], lu[1], lu[2], lu[3]};
    __nv_bfloat16* row = Y + r * (size_t)(3 * C);
    *(ushort4*)(row + c)         = h4;
    *(ushort4*)(row + C + c)     = h4;
    *(ushort4*)(row + 2 * C + c) = l4;
}

__global__ void __launch_bounds__(256) split_b_kernel(
    const float* __restrict__ W, __nv_bfloat16* __restrict__ Y, int K, int nmask, int nshift)
{
    const size_t i4 = ((size_t)blockIdx.x * 256 + threadIdx.x) * 4;
    const int N = nmask + 1;
    const size_t r = i4 >> nshift;
    const int c = (int)(i4 & nmask);
    float4 x = *(const float4*)(W + i4);
    float xs[4] = {x.x, x.y, x.z, x.w};
    unsigned short hu[4], lu[4];
    #pragma unroll
    for (int t = 0; t < 4; t++) {
        __nv_bfloat16 hh = __float2bfloat16(xs[t]);
        __nv_bfloat16 ll = __float2bfloat16(xs[t] - __bfloat162float(hh));
        hu[t] = *(unsigned short*)&hh; lu[t] = *(unsigned short*)&ll;
    }
    ushort4 h4 = {hu[0], hu[1], hu[2], hu[3]};
    ushort4 l4 = {lu[0], lu[1], lu[2], lu[3]};
    *(ushort4*)(Y + r * (size_t)N + c)             = h4;  // Bh
    *(ushort4*)(Y + ((size_t)K + r) * N + c)       = l4;  // Bl
    *(ushort4*)(Y + ((size_t)(2 * K) + r) * N + c) = h4;  // Bh
}

// ================= bf16 tensor-core GEMM (BM=128, BN=128, BK=32, 4-stage) ==========
// 8 warps as 4x2; warp tile 32x64. Single barrier per mainloop iteration.
#define HG_ABUF (128 * 40 * 2)              // 10240 B per stage
#define HG_BBUF (32 * 136 * 2)              // 8704 B per stage
#define HG_STAGE (HG_ABUF + HG_BBUF)        // 18944 B
#define HG_SMEM (4 * HG_STAGE)              // 75776 B

// EPI: 0 = bias, 1 = bias + exact gelu.  EMIT: write [h|h|l] split to Sp (stride 3N).
// C may be null when EMIT=1 (split-only output).
template<int EPI, int EMIT>
__global__ void __launch_bounds__(256) hgemm_kernel(
    const __nv_bfloat16* __restrict__ A, const __nv_bfloat16* __restrict__ Bw,
    const float* __restrict__ bias, float* __restrict__ C,
    __nv_bfloat16* __restrict__ Sp, int N, int Kp)
{
    extern __shared__ __align__(16) char hsm[];
    const int tid  = threadIdx.x;
    const int wid  = tid >> 5, lane = tid & 31;
    const int wm   = (wid >> 1) * 32, wn = (wid & 1) * 64;
    const int bm   = blockIdx.y * 128, bn = blockIdx.x * 128;

    auto Arow = [&](int buf, int r) {
        return (__nv_bfloat16*)(hsm + buf * HG_STAGE) + r * 40;
    };
    auto Brow = [&](int buf, int r) {
        return (__nv_bfloat16*)(hsm + buf * HG_STAGE + HG_ABUF) + r * 136;
    };

    float acc[2][8][4];
    #pragma unroll
    for (int f = 0; f < 2; f++)
        #pragma unroll
        for (int p = 0; p < 8; p++)
            #pragma unroll
            for (int t = 0; t < 4; t++) acc[f][p][t] = 0.f;

    auto issue_tile = [&](int buf, int k0) {
        #pragma unroll
        for (int t = 0; t < 2; t++) {
            int idx = tid + t * 256;
            int ar = idx >> 2, ac = (idx & 3) * 8;
            cp_async16(Arow(buf, ar) + ac, A + (size_t)(bm + ar) * Kp + k0 + ac);
        }
        #pragma unroll
        for (int t = 0; t < 2; t++) {
            int idx = tid + t * 256;
            int br = idx >> 4, bc = (idx & 15) * 8;
            cp_async16(Brow(buf, br) + bc, Bw + (size_t)(k0 + br) * N + bn + bc);
        }
        asm volatile("cp.async.commit_group;\n" ::: "memory");
    };

    const int NIT = Kp / 32;
    issue_tile(0, 0);
    issue_tile(1, 32);
    issue_tile(2, 64);

    for (int it = 0; it < NIT; it++) {
        if (it <= NIT - 3)      { asm volatile("cp.async.wait_group 2;\n" ::: "memory"); }
        else if (it == NIT - 2) { asm volatile("cp.async.wait_group 1;\n" ::: "memory"); }
        else                    { asm volatile("cp.async.wait_group 0;\n" ::: "memory"); }
        __syncthreads();

        const int buf = it & 3;
        #pragma unroll
        for (int kk = 0; kk < 32; kk += 16) {
            unsigned af[2][4];
            #pragma unroll
            for (int f = 0; f < 2; f++) {
                int row = wm + f * 16 + (lane & 15);
                int col = kk + (lane >> 4) * 8;
                LDSM4(af[f][0], af[f][1], af[f][2], af[f][3], Arow(buf, row) + col);
            }
            unsigned bfr[8][2];
            #pragma unroll
            for (int p = 0; p < 4; p++) {
                int krow = kk + (lane & 7) + ((lane >> 3) & 1) * 8;
                int ncol = wn + p * 16 + (lane >> 4) * 8;
                unsigned r0, r1, r2, r3;
                LDSM4T(r0, r1, r2, r3, Brow(buf, krow) + ncol);
                bfr[p*2][0] = r0; bfr[p*2][1] = r1; bfr[p*2+1][0] = r2; bfr[p*2+1][1] = r3;
            }
            #pragma unroll
            for (int f = 0; f < 2; f++)
                #pragma unroll
                for (int p = 0; p < 8; p++)
                    MMA16816(acc[f][p], af[f][0], af[f][1], af[f][2], af[f][3],
                             bfr[p][0], bfr[p][1]);
        }

        // issue chunk it+3 into buf (it+3)&3 == (it-1)&3: all warps finished reading it
        // at this iteration's top barrier.
        if (it + 3 < NIT) issue_tile((it + 3) & 3, (it + 3) * 32);
    }

    const int r0 = lane >> 2, c0 = (lane & 3) * 2;
    #pragma unroll
    for (int f = 0; f < 2; f++) {
        #pragma unroll
        for (int p = 0; p < 8; p++) {
            const int grow = bm + wm + f * 16 + r0;
            const int gcol = bn + wn + p * 8 + c0;
            const float b0 = bias[gcol], b1 = bias[gcol + 1];
            float v00 = acc[f][p][0] + b0, v01 = acc[f][p][1] + b1;
            float v10 = acc[f][p][2] + b0, v11 = acc[f][p][3] + b1;
            if (EPI == 1) {
                v00 = 0.5f * v00 * (1.0f + erff(v00 * 0.70710678118654752f));
                v01 = 0.5f * v01 * (1.0f + erff(v01 * 0.70710678118654752f));
                v10 = 0.5f * v10 * (1.0f + erff(v10 * 0.70710678118654752f));
                v11 = 0.5f * v11 * (1.0f + erff(v11 * 0.70710678118654752f));
            }
            if (!EMIT || C) {
                float2 lo = {v00, v01}, hi = {v10, v11};
                *(float2*)(C + (size_t)grow * N + gcol)       = lo;
                *(float2*)(C + (size_t)(grow + 8) * N + gcol) = hi;
            }
            if (EMIT) {
                emit_split_pair(Sp + (size_t)grow * (3 * N),       N, gcol, v00, v01);
                emit_split_pair(Sp + (size_t)(grow + 8) * (3 * N), N, gcol, v10, v11);
            }
        }
    }
}

// ================= tensor-core flash attention (emits split output) =================
struct FlashSmem {
    __nv_bfloat16 Q2[128][136];
    __nv_bfloat16 K2[32][136];
    __nv_bfloat16 V2[64][72];
    __nv_bfloat16 P2[128][72];
    float msk[32];
};

__global__ void __launch_bounds__(256) flash_attn_tc_kernel(
    const float* __restrict__ Q, const float* __restrict__ Kx,
    const float* __restrict__ V, const float* __restrict__ mask,
    __nv_bfloat16* __restrict__ Osp, int Lq, int Lk, float scale)
{
    extern __shared__ char fsm_raw[];
    FlashSmem* sm = (FlashSmem*)fsm_raw;

    const int bh = blockIdx.y;
    const int b = bh >> 4, h = bh & 15;
    const int q0 = blockIdx.x * 128;
    const int tid = threadIdx.x, wid = tid >> 5, lane = tid & 31;
    const int r0 = lane >> 2;
    const int cc = (lane & 3) * 2;

    #pragma unroll
    for (int it = 0; it < 8; it++) {
        int idx = tid + it * 256;
        int r = idx >> 4, c4 = (idx & 15) * 4;
        float4 qv = *(const float4*)(Q + (size_t)(b*Lq + q0 + r) * D + h*HD + c4);
        float xs[4] = {qv.x, qv.y, qv.z, qv.w};
        unsigned short hu[4], lu[4];
        #pragma unroll
        for (int t = 0; t < 4; t++) {
            __nv_bfloat16 hh = __float2bfloat16(xs[t]);
            __nv_bfloat16 ll = __float2bfloat16(xs[t] - __bfloat162float(hh));
            hu[t] = *(unsigned short*)&hh; lu[t] = *(unsigned short*)&ll;
        }
        ushort4 h4 = {hu[0], hu[1], hu[2], hu[3]};
        ushort4 l4 = {lu[0], lu[1], lu[2], lu[3]};
        *(ushort4*)&sm->Q2[r][c4]      = h4;
        *(ushort4*)&sm->Q2[r][64 + c4] = l4;
    }

    float m0 = -1e30f, m1 = -1e30f, l0 = 0.f, l1 = 0.f;
    float o[8][4];
    #pragma unroll
    for (int d = 0; d < 8; d++)
        #pragma unroll
        for (int t = 0; t < 4; t++) o[d][t] = 0.f;

    for (int k0 = 0; k0 < Lk; k0 += 32) {
        __syncthreads();

        #pragma unroll
        for (int it = 0; it < 2; it++) {
            int idx = tid + it * 256;
            int r = idx >> 4, c4 = (idx & 15) * 4;
            const size_t g = (size_t)(b*Lk + k0 + r) * D + h*HD + c4;
            float4 kv = *(const float4*)(Kx + g);
            float4 vv = *(const float4*)(V + g);
            float ks[4] = {kv.x, kv.y, kv.z, kv.w};
            float vs[4] = {vv.x, vv.y, vv.z, vv.w};
            unsigned short khu[4], klu[4], vhu[4], vlu[4];
            #pragma unroll
            for (int t = 0; t < 4; t++) {
                __nv_bfloat16 hh = __float2bfloat16(ks[t]);
                __nv_bfloat16 ll = __float2bfloat16(ks[t] - __bfloat162float(hh));
                khu[t] = *(unsigned short*)&hh; klu[t] = *(unsigned short*)&ll;
                hh = __float2bfloat16(vs[t]);
                ll = __float2bfloat16(vs[t] - __bfloat162float(hh));
                vhu[t] = *(unsigned short*)&hh; vlu[t] = *(unsigned short*)&ll;
            }
            ushort4 kh4 = {khu[0], khu[1], khu[2], khu[3]};
            ushort4 kl4 = {klu[0], klu[1], klu[2], klu[3]};
            ushort4 vh4 = {vhu[0], vhu[1], vhu[2], vhu[3]};
            ushort4 vl4 = {vlu[0], vlu[1], vlu[2], vlu[3]};
            *(ushort4*)&sm->K2[r][c4]      = kh4;
            *(ushort4*)&sm->K2[r][64 + c4] = kl4;
            *(ushort4*)&sm->V2[r][c4]      = vh4;
            *(ushort4*)&sm->V2[32 + r][c4] = vl4;
        }
        if (tid < 32) sm->msk[tid] = mask ? mask[(size_t)b * Lk + k0 + tid] : 0.f;
        __syncthreads();

        float sf[4][4];
        #pragma unroll
        for (int nb = 0; nb < 4; nb++)
            #pragma unroll
            for (int t = 0; t < 4; t++) sf[nb][t] = 0.f;

        const int qc[12] = {0,16,32,48, 0,16,32,48, 64,80,96,112};
        const int kc[12] = {0,16,32,48, 64,80,96,112, 0,16,32,48};
        #pragma unroll
        for (int s = 0; s < 12; s++) {
            unsigned af[4];
            LDSM4(af[0], af[1], af[2], af[3],
                  &sm->Q2[wid*16 + (lane & 15)][qc[s] + (lane >> 4) * 8]);
            #pragma unroll
            for (int nb = 0; nb < 2; nb++) {
                unsigned t0, t1, t2, t3;
                LDSM4(t0, t1, t2, t3,
                      &sm->K2[nb*16 + (lane & 15)][kc[s] + (lane >> 4) * 8]);
                MMA16816(sf[nb*2],     af[0], af[1], af[2], af[3], t0, t2);
                MMA16816(sf[nb*2 + 1], af[0], af[1], af[2], af[3], t1, t3);
            }
        }

        #pragma unroll
        for (int nb = 0; nb < 4; nb++) {
            float mv0 = sm->msk[nb*8 + cc], mv1 = sm->msk[nb*8 + cc + 1];
            sf[nb][0] = sf[nb][0] * scale + mv0;
            sf[nb][1] = sf[nb][1] * scale + mv1;
            sf[nb][2] = sf[nb][2] * scale + mv0;
            sf[nb][3] = sf[nb][3] * scale + mv1;
        }

        float tm0 = -1e30f, tm1 = -1e30f;
        #pragma unroll
        for (int nb = 0; nb < 4; nb++) {
            tm0 = fmaxf(tm0, fmaxf(sf[nb][0], sf[nb][1]));
            tm1 = fmaxf(tm1, fmaxf(sf[nb][2], sf[nb][3]));
        }
        tm0 = fmaxf(tm0, __shfl_xor_sync(0xffffffffu, tm0, 1));
        tm0 = fmaxf(tm0, __shfl_xor_sync(0xffffffffu, tm0, 2));
        tm1 = fmaxf(tm1, __shfl_xor_sync(0xffffffffu, tm1, 1));
        tm1 = fmaxf(tm1, __shfl_xor_sync(0xffffffffu, tm1, 2));

        const float nm0 = fmaxf(m0, tm0), nm1 = fmaxf(m1, tm1);
        const float corr0 = __expf(m0 - nm0), corr1 = __expf(m1 - nm1);
        m0 = nm0; m1 = nm1;

        float ts0 = 0.f, ts1 = 0.f;
        #pragma unroll
        for (int nb = 0; nb < 4; nb++) {
            sf[nb][0] = __expf(sf[nb][0] - nm0);
            sf[nb][1] = __expf(sf[nb][1] - nm0);
            sf[nb][2] = __expf(sf[nb][2] - nm1);
            sf[nb][3] = __expf(sf[nb][3] - nm1);
            ts0 += sf[nb][0] + sf[nb][1];
            ts1 += sf[nb][2] + sf[nb][3];
        }
        ts0 += __shfl_xor_sync(0xffffffffu, ts0, 1);
        ts0 += __shfl_xor_sync(0xffffffffu, ts0, 2);
        ts1 += __shfl_xor_sync(0xffffffffu, ts1, 1);
        ts1 += __shfl_xor_sync(0xffffffffu, ts1, 2);
        l0 = l0 * corr0 + ts0;
        l1 = l1 * corr1 + ts1;

        const int pr0 = wid*16 + r0, pr1 = pr0 + 8;
        #pragma unroll
        for (int nb = 0; nb < 4; nb++) {
            #pragma unroll
            for (int half = 0; half < 2; half++) {
                const int prow = half ? pr1 : pr0;
                float p0 = sf[nb][half*2], p1 = sf[nb][half*2 + 1];
                __nv_bfloat16 h0 = __float2bfloat16(p0);
                __nv_bfloat16 h1 = __float2bfloat16(p1);
                __nv_bfloat16 e0 = __float2bfloat16(p0 - __bfloat162float(h0));
                __nv_bfloat16 e1 = __float2bfloat16(p1 - __bfloat162float(h1));
                unsigned ph = (unsigned)*(unsigned short*)&h0 |
                              ((unsigned)*(unsigned short*)&h1 << 16);
                unsigned pl = (unsigned)*(unsigned short*)&e0 |
                              ((unsigned)*(unsigned short*)&e1 << 16);
                *(unsigned*)&sm->P2[prow][nb*8 + cc]      = ph;
                *(unsigned*)&sm->P2[prow][32 + nb*8 + cc] = pl;
            }
        }

        #pragma unroll
        for (int d = 0; d < 8; d++) {
            o[d][0] *= corr0; o[d][1] *= corr0;
            o[d][2] *= corr1; o[d][3] *= corr1;
        }
        __syncthreads();

        const int pc[6] = {0, 16, 32, 48, 0, 16};
        const int vc[6] = {0, 16, 0, 16, 32, 48};
        #pragma unroll
        for (int s = 0; s < 6; s++) {
            unsigned af[4];
            LDSM4(af[0], af[1], af[2], af[3],
                  &sm->P2[wid*16 + (lane & 15)][pc[s] + (lane >> 4) * 8]);
            #pragma unroll
            for (int p = 0; p < 4; p++) {
                unsigned t0, t1, t2, t3;
                int krow = vc[s] + (lane & 7) + ((lane >> 3) & 1) * 8;
                int ncol = p*16 + (lane >> 4) * 8;
                LDSM4T(t0, t1, t2, t3, &sm->V2[krow][ncol]);
                MMA16816(o[p*2],     af[0], af[1], af[2], af[3], t0, t1);
                MMA16816(o[p*2 + 1], af[0], af[1], af[2], af[3], t2, t3);
            }
        }
    }

    // normalize + emit split directly (att fp32 never materialized)
    const float li0 = 1.f / l0, li1 = 1.f / l1;
    const int gq0 = b*Lq + q0 + wid*16 + r0;
    #pragma unroll
    for (int d = 0; d < 8; d++) {
        const int col = h*HD + d*8 + cc;
        emit_split_pair(Osp + (size_t)gq0 * (3*D),       D, col, o[d][0]*li0, o[d][1]*li0);
        emit_split_pair(Osp + (size_t)(gq0 + 8) * (3*D), D, col, o[d][2]*li1, o[d][3]*li1);
    }
}

// ================= residual + LayerNorm (optional split emission) =================
__global__ void __launch_bounds__(256) ln_residual_kernel(
    const float* __restrict__ Y, const float* __restrict__ R,
    const float* __restrict__ g, const float* __restrict__ be,
    float* __restrict__ O, __nv_bfloat16* __restrict__ Sp)
{
    const size_t row = blockIdx.x;
    const int tid = threadIdx.x;
    const float* y = Y + row * D;
    const float* r = R + row * D;
    __shared__ float red[256];

    float h[4];
    float s = 0.f;
    #pragma unroll
    for (int i = 0; i < 4; i++) {
        h[i] = y[tid + i*256] + r[tid + i*256];
        s += h[i];
    }
    red[tid] = s; __syncthreads();
    for (int st = 128; st > 0; st >>= 1) {
        if (tid < st) red[tid] += red[tid + st];
        __syncthreads();
    }
    const float mean = red[0] * (1.0f / D);
    __syncthreads();

    float vs = 0.f;
    #pragma unroll
    for (int i = 0; i < 4; i++) {
        float dd = h[i] - mean;
        vs += dd * dd;
    }
    red[tid] = vs; __syncthreads();
    for (int st = 128; st > 0; st >>= 1) {
        if (tid < st) red[tid] += red[tid + st];
        __syncthreads();
    }
    const float inv = rsqrtf(red[0] * (1.0f / D) + 1e-5f);

    __nv_bfloat16* sprow = Sp ? Sp + row * (size_t)(3 * D) : nullptr;
    #pragma unroll
    for (int i = 0; i < 4; i++) {
        const int c = tid + i*256;
        const float v = (h[i] - mean) * inv * g[c] + be[c];
        O[row * D + c] = v;
        if (sprow) {
            __nv_bfloat16 hh = __float2bfloat16(v);
            __nv_bfloat16 ll = __float2bfloat16(v - __bfloat162float(hh));
            sprow[c]         = hh;
            sprow[D + c]     = hh;
            sprow[2 * D + c] = ll;
        }
    }
}

// ================= host launch =================
extern "C" void kernel_launch(void* const* d_in, const int* in_sizes, int n_in,
                              void* d_out, int out_size)
{
    const float* input = (const float*)d_in[0];
    const float* ctx   = (const float*)d_in[1];
    const float* mask  = (const float*)d_in[2];
    const float* cq_w = (const float*)d_in[3];  const float* cq_b = (const float*)d_in[4];
    const float* ck_w = (const float*)d_in[5];  const float* ck_b = (const float*)d_in[6];
    const float* cv_w = (const float*)d_in[7];  const float* cv_b = (const float*)d_in[8];
    const float* co_w = (const float*)d_in[9];  const float* co_b = (const float*)d_in[10];
    const float* co_g = (const float*)d_in[11]; const float* co_be= (const float*)d_in[12];
    const float* sq_w = (const float*)d_in[13]; const float* sq_b = (const float*)d_in[14];
    const float* sk_w = (const float*)d_in[15]; const float* sk_b = (const float*)d_in[16];
    const float* sv_w = (const float*)d_in[17]; const float* sv_b = (const float*)d_in[18];
    const float* so_w = (const float*)d_in[19]; const float* so_b = (const float*)d_in[20];
    const float* so_g = (const float*)d_in[21]; const float* so_be= (const float*)d_in[22];
    const float* fi_w = (const float*)d_in[23]; const float* fi_b = (const float*)d_in[24];
    const float* fo_w = (const float*)d_in[25]; const float* fo_b = (const float*)d_in[26];
    const float* fo_g = (const float*)d_in[27]; const float* fo_be= (const float*)d_in[28];

    float *q, *k, *v, *x, *x2, *y;
    __nv_bfloat16 *sa, *sa2, *sb;
    cudaGetSymbolAddress((void**)&q,    g_q);
    cudaGetSymbolAddress((void**)&k,    g_k);
    cudaGetSymbolAddress((void**)&v,    g_v);
    cudaGetSymbolAddress((void**)&x,    g_x);
    cudaGetSymbolAddress((void**)&x2,   g_x2);
    cudaGetSymbolAddress((void**)&y,    g_y);
    cudaGetSymbolAddress((void**)&sa,   g_sa);
    cudaGetSymbolAddress((void**)&sa2,  g_sa2);
    cudaGetSymbolAddress((void**)&sb,   g_sb);

    const float scale = 0.125f; // 1/sqrt(64)
    dim3 blk(256);
    const int FLASH_SMEM = (int)sizeof(FlashSmem);
    static int smem_set = 0;
    if (!smem_set) {
        cudaFuncSetAttribute(flash_attn_tc_kernel,
                             cudaFuncAttributeMaxDynamicSharedMemorySize, FLASH_SMEM);
        cudaFuncSetAttribute(hgemm_kernel<0,0>,
                             cudaFuncAttributeMaxDynamicSharedMemorySize, HG_SMEM);
        cudaFuncSetAttribute(hgemm_kernel<1,1>,
                             cudaFuncAttributeMaxDynamicSharedMemorySize, HG_SMEM);
        smem_set = 1;
    }

    #define SPLIT_A(X, R, C, SH)  split_a_kernel<<<((size_t)(R)*(C))/1024, blk>>>((X), sa2, (C)-1, (SH))
    #define SPLIT_B(W, K_, N_, SH) split_b_kernel<<<((size_t)(K_)*(N_))/1024, blk>>>((W), sb, (K_), (N_)-1, (SH))
    #define GEMM(BIAS, OUT, M_, N_, K3) \
        hgemm_kernel<0,0><<<dim3((N_)/128, (M_)/128), blk, HG_SMEM>>>(sa2, sb, (BIAS), (OUT), nullptr, (N_), (K3))

    // ---- cross attention ----
    SPLIT_A(input, MQ, D, 10);
    SPLIT_B(cq_w, D, D, 10);  GEMM(cq_b, q, MQ, D, 3*D);
    SPLIT_A(ctx, MCTX, D, 10);
    SPLIT_B(ck_w, D, D, 10);  GEMM(ck_b, k, MCTX, D, 3*D);
    SPLIT_B(cv_w, D, D, 10);  GEMM(cv_b, v, MCTX, D, 3*D);

    // flash emits att split directly into sa2 (ctx split already consumed)
    flash_attn_tc_kernel<<<dim3(LQ/128, B*H), blk, FLASH_SMEM>>>(q, k, v, mask, sa2, LQ, LK, scale);

    SPLIT_B(co_w, D, D, 10);  GEMM(co_b, y, MQ, D, 3*D);
    ln_residual_kernel<<<MQ, blk>>>(y, input, co_g, co_be, x, sa2);   // emits x split

    // ---- self attention ----
    SPLIT_B(sq_w, D, D, 10);  GEMM(sq_b, q, MQ, D, 3*D);
    SPLIT_B(sk_w, D, D, 10);  GEMM(sk_b, k, MQ, D, 3*D);
    SPLIT_B(sv_w, D, D, 10);  GEMM(sv_b, v, MQ, D, 3*D);

    flash_attn_tc_kernel<<<dim3(LQ/128, B*H), blk, FLASH_SMEM>>>(q, k, v, nullptr, sa2, LQ, LQ, scale);

    SPLIT_B(so_w, D, D, 10);  GEMM(so_b, y, MQ, D, 3*D);
    ln_residual_kernel<<<MQ, blk>>>(y, x, so_g, so_be, x2, sa2);      // emits x2 split

    // ---- FFN ----
    SPLIT_B(fi_w, D, F, 12);
    // fi: reads x2 split (sa2), emits inter split to sa, no fp32 output
    hgemm_kernel<1,1><<<dim3(F/128, MQ/128), blk, HG_SMEM>>>(sa2, sb, fi_b, nullptr, sa, F, 3*D);
    SPLIT_B(fo_w, F, D, 10);
    hgemm_kernel<0,0><<<dim3(D/128, MQ/128), blk, HG_SMEM>>>(sa, sb, fo_b, y, nullptr, D, 3*F);
    ln_residual_kernel<<<MQ, blk>>>(y, x2, fo_g, fo_be, (float*)d_out, nullptr);

    #undef SPLIT_A
    #undef SPLIT_B
    #undef GEMM
}

// round 16
// speedup vs baseline: 1.7989x; 1.0263x over previous
#include <cuda_runtime.h>
#include <cuda_bf16.h>
#include <cstdint>
#include <stdint.h>
#include <math.h>

// ---------------- problem constants ----------------
#define B    4
#define LQ   1024
#define LK   2048
#define D    1024
#define H    16
#define HD   64
#define F    4096
#define MQ   (B*LQ)     // 4096
#define MCTX (B*LK)     // 8192

// ---------------- scratch (static __device__, no allocs) ----------------
__device__ float g_q   [(size_t)MQ * D];                 // cross Q
__device__ float g_kv  [(size_t)MCTX * 2 * D];           // packed cross KV / self QKV
__device__ float g_x   [(size_t)MQ * D];
__device__ float g_x2  [(size_t)MQ * D];
__device__ float g_y   [(size_t)MQ * D];
__device__ __nv_bfloat16 g_sa  [(size_t)MQ * 3 * F];     // inter split (fi -> fo)
__device__ __nv_bfloat16 g_sa2 [(size_t)MCTX * 3 * D];   // all D-wide A splits
__device__ __nv_bfloat16 g_sb  [(size_t)3 * F * D];      // B' split buffer (concat-capable)

// ---------------- asm helpers ----------------
__device__ __forceinline__ unsigned smem_u32(const void* p) {
    return (unsigned)__cvta_generic_to_shared(p);
}

#define LDSM4(R0,R1,R2,R3,PTR) do { \
    unsigned _a = smem_u32(PTR); \
    asm volatile("ldmatrix.sync.aligned.m8n8.x4.shared.b16 {%0,%1,%2,%3}, [%4];" \
        : "=r"(R0),"=r"(R1),"=r"(R2),"=r"(R3) : "r"(_a)); } while(0)

#define LDSM4T(R0,R1,R2,R3,PTR) do { \
    unsigned _a = smem_u32(PTR); \
    asm volatile("ldmatrix.sync.aligned.m8n8.x4.trans.shared.b16 {%0,%1,%2,%3}, [%4];" \
        : "=r"(R0),"=r"(R1),"=r"(R2),"=r"(R3) : "r"(_a)); } while(0)

#define MMA16816(C,A0,A1,A2,A3,B0,B1) \
    asm volatile("mma.sync.aligned.m16n8k16.row.col.f32.bf16.bf16.f32 " \
        "{%0,%1,%2,%3},{%4,%5,%6,%7},{%8,%9},{%0,%1,%2,%3};" \
        : "+f"((C)[0]), "+f"((C)[1]), "+f"((C)[2]), "+f"((C)[3]) \
        : "r"(A0), "r"(A1), "r"(A2), "r"(A3), "r"(B0), "r"(B1))

__device__ __forceinline__ void cp_async16(void* smem, const void* gmem) {
    unsigned s = smem_u32(smem);
    asm volatile("cp.async.cg.shared.global [%0], [%1], 16;\n" :: "r"(s), "l"(gmem));
}

// emit split pair (2 consecutive cols) to a split row: [h,h,l] at col, C+col, 2C+col
__device__ __forceinline__ void emit_split_pair(
    __nv_bfloat16* row, int C, int col, float a, float b)
{
    __nv_bfloat16 h0 = __float2bfloat16(a), h1 = __float2bfloat16(b);
    __nv_bfloat16 l0 = __float2bfloat16(a - __bfloat162float(h0));
    __nv_bfloat16 l1 = __float2bfloat16(b - __bfloat162float(h1));
    unsigned hp = (unsigned)*(unsigned short*)&h0 | ((unsigned)*(unsigned short*)&h1 << 16);
    unsigned lp = (unsigned)*(unsigned short*)&l0 | ((unsigned)*(unsigned short*)&l1 << 16);
    *(unsigned*)(row + col)         = hp;
    *(unsigned*)(row + C + col)     = hp;
    *(unsigned*)(row + 2 * C + col) = lp;
}

// ================= bf16 split conversion (external inputs only) =================
__global__ void __launch_bounds__(256) split_a_kernel(
    const float* __restrict__ X, __nv_bfloat16* __restrict__ Y, int cmask, int cshift)
{
    const size_t i4 = ((size_t)blockIdx.x * 256 + threadIdx.x) * 4;
    const int C = cmask + 1;
    const size_t r = i4 >> cshift;
    const int c = (int)(i4 & cmask);
    float4 x = *(const float4*)(X + i4);
    float xs[4] = {x.x, x.y, x.z, x.w};
    unsigned short hu[4], lu[4];
    #pragma unroll
    for (int t = 0; t < 4; t++) {
        __nv_bfloat16 hh = __float2bfloat16(xs[t]);
        __nv_bfloat16 ll = __float2bfloat16(xs[t] - __bfloat162float(hh));
        hu[t] = *(unsigned short*)&hh; lu[t] = *(unsigned short*)&ll;
    }
    ushort4 h4 = {hu[0], hu[1], hu[2], hu[3]};
    ushort4 l4 = {lu[0], lu[1], lu[2], lu[3]};
    __nv_bfloat16* row = Y + r * (size_t)(3 * C);
    *(ushort4*)(row + c)         = h4;
    *(ushort4*)(row + C + c)     = h4;
    *(ushort4*)(row + 2 * C + c) = l4;
}

// W[K,N] fp32 -> rows [0,K)=Bh, [K,2K)=Bl, [2K,3K)=Bh of Y, at column offset c0,
// row stride Ntot (for concatenated multi-weight B').
__global__ void __launch_bounds__(256) split_b_kernel(
    const float* __restrict__ W, __nv_bfloat16* __restrict__ Y, int K,
    int nmask, int nshift, int c0, int Ntot)
{
    const size_t i4 = ((size_t)blockIdx.x * 256 + threadIdx.x) * 4;
    const int N = nmask + 1;
    const size_t r = i4 >> nshift;
    const int c = (int)(i4 & nmask);
    float4 x = *(const float4*)(W + i4);
    float xs[4] = {x.x, x.y, x.z, x.w};
    unsigned short hu[4], lu[4];
    #pragma unroll
    for (int t = 0; t < 4; t++) {
        __nv_bfloat16 hh = __float2bfloat16(xs[t]);
        __nv_bfloat16 ll = __float2bfloat16(xs[t] - __bfloat162float(hh));
        hu[t] = *(unsigned short*)&hh; lu[t] = *(unsigned short*)&ll;
    }
    ushort4 h4 = {hu[0], hu[1], hu[2], hu[3]};
    ushort4 l4 = {lu[0], lu[1], lu[2], lu[3]};
    (void)N;
    *(ushort4*)(Y + r * (size_t)Ntot + c0 + c)             = h4;  // Bh
    *(ushort4*)(Y + ((size_t)K + r) * Ntot + c0 + c)       = l4;  // Bl
    *(ushort4*)(Y + ((size_t)(2 * K) + r) * Ntot + c0 + c) = h4;  // Bh
}

// ================= bf16 tensor-core GEMM (BM=128, BN=128, BK=32, 4-stage) ==========
#define HG_ABUF (128 * 40 * 2)              // 10240 B per stage
#define HG_BBUF (32 * 136 * 2)              // 8704 B per stage
#define HG_STAGE (HG_ABUF + HG_BBUF)        // 18944 B
#define HG_SMEM (4 * HG_STAGE)              // 75776 B

// EPI: 0=bias, 1=bias+gelu. EMIT: write [h|h|l] split to Sp (stride 3N).
// NSEG: bias segments of width 1024 (1 => single bias over all N).
template<int EPI, int EMIT, int NSEG>
__global__ void __launch_bounds__(256) hgemm_kernel(
    const __nv_bfloat16* __restrict__ A, const __nv_bfloat16* __restrict__ Bw,
    const float* __restrict__ bias0, const float* __restrict__ bias1,
    const float* __restrict__ bias2, float* __restrict__ C,
    __nv_bfloat16* __restrict__ Sp, int N, int Kp)
{
    extern __shared__ __align__(16) char hsm[];
    const int tid  = threadIdx.x;
    const int wid  = tid >> 5, lane = tid & 31;
    const int wm   = (wid >> 1) * 32, wn = (wid & 1) * 64;
    const int bm   = blockIdx.y * 128, bn = blockIdx.x * 128;

    auto Arow = [&](int buf, int r) {
        return (__nv_bfloat16*)(hsm + buf * HG_STAGE) + r * 40;
    };
    auto Brow = [&](int buf, int r) {
        return (__nv_bfloat16*)(hsm + buf * HG_STAGE + HG_ABUF) + r * 136;
    };

    float acc[2][8][4];
    #pragma unroll
    for (int f = 0; f < 2; f++)
        #pragma unroll
        for (int p = 0; p < 8; p++)
            #pragma unroll
            for (int t = 0; t < 4; t++) acc[f][p][t] = 0.f;

    auto issue_tile = [&](int buf, int k0) {
        #pragma unroll
        for (int t = 0; t < 2; t++) {
            int idx = tid + t * 256;
            int ar = idx >> 2, ac = (idx & 3) * 8;
            cp_async16(Arow(buf, ar) + ac, A + (size_t)(bm + ar) * Kp + k0 + ac);
        }
        #pragma unroll
        for (int t = 0; t < 2; t++) {
            int idx = tid + t * 256;
            int br = idx >> 4, bc = (idx & 15) * 8;
            cp_async16(Brow(buf, br) + bc, Bw + (size_t)(k0 + br) * N + bn + bc);
        }
        asm volatile("cp.async.commit_group;\n" ::: "memory");
    };

    const int NIT = Kp / 32;
    issue_tile(0, 0);
    issue_tile(1, 32);
    issue_tile(2, 64);

    for (int it = 0; it < NIT; it++) {
        if (it <= NIT - 3)      { asm volatile("cp.async.wait_group 2;\n" ::: "memory"); }
        else if (it == NIT - 2) { asm volatile("cp.async.wait_group 1;\n" ::: "memory"); }
        else                    { asm volatile("cp.async.wait_group 0;\n" ::: "memory"); }
        __syncthreads();

        const int buf = it & 3;
        #pragma unroll
        for (int kk = 0; kk < 32; kk += 16) {
            unsigned af[2][4];
            #pragma unroll
            for (int f = 0; f < 2; f++) {
                int row = wm + f * 16 + (lane & 15);
                int col = kk + (lane >> 4) * 8;
                LDSM4(af[f][0], af[f][1], af[f][2], af[f][3], Arow(buf, row) + col);
            }
            unsigned bfr[8][2];
            #pragma unroll
            for (int p = 0; p < 4; p++) {
                int krow = kk + (lane & 7) + ((lane >> 3) & 1) * 8;
                int ncol = wn + p * 16 + (lane >> 4) * 8;
                unsigned r0, r1, r2, r3;
                LDSM4T(r0, r1, r2, r3, Brow(buf, krow) + ncol);
                bfr[p*2][0] = r0; bfr[p*2][1] = r1; bfr[p*2+1][0] = r2; bfr[p*2+1][1] = r3;
            }
            #pragma unroll
            for (int f = 0; f < 2; f++)
                #pragma unroll
                for (int p = 0; p < 8; p++)
                    MMA16816(acc[f][p], af[f][0], af[f][1], af[f][2], af[f][3],
                             bfr[p][0], bfr[p][1]);
        }

        if (it + 3 < NIT) issue_tile((it + 3) & 3, (it + 3) * 32);
    }

    const int r0 = lane >> 2, c0 = (lane & 3) * 2;
    #pragma unroll
    for (int f = 0; f < 2; f++) {
        #pragma unroll
        for (int p = 0; p < 8; p++) {
            const int grow = bm + wm + f * 16 + r0;
            const int gcol = bn + wn + p * 8 + c0;
            const float* bp = bias0;
            int bcol = gcol;
            if (NSEG > 1) {
                const int seg = gcol >> 10;
                bp = (seg == 0) ? bias0 : ((seg == 1) ? bias1 : bias2);
                bcol = gcol & 1023;
            }
            const float b0 = bp[bcol], b1 = bp[bcol + 1];
            float v00 = acc[f][p][0] + b0, v01 = acc[f][p][1] + b1;
            float v10 = acc[f][p][2] + b0, v11 = acc[f][p][3] + b1;
            if (EPI == 1) {
                v00 = 0.5f * v00 * (1.0f + erff(v00 * 0.70710678118654752f));
                v01 = 0.5f * v01 * (1.0f + erff(v01 * 0.70710678118654752f));
                v10 = 0.5f * v10 * (1.0f + erff(v10 * 0.70710678118654752f));
                v11 = 0.5f * v11 * (1.0f + erff(v11 * 0.70710678118654752f));
            }
            if (!EMIT || C) {
                float2 lo = {v00, v01}, hi = {v10, v11};
                *(float2*)(C + (size_t)grow * N + gcol)       = lo;
                *(float2*)(C + (size_t)(grow + 8) * N + gcol) = hi;
            }
            if (EMIT) {
                emit_split_pair(Sp + (size_t)grow * (3 * N),       N, gcol, v00, v01);
                emit_split_pair(Sp + (size_t)(grow + 8) * (3 * N), N, gcol, v10, v11);
            }
        }
    }
}

// ================= tensor-core flash attention (strided QKV, emits split) =========
struct FlashSmem {
    __nv_bfloat16 Q2[128][136];
    __nv_bfloat16 K2[32][136];
    __nv_bfloat16 V2[64][72];
    __nv_bfloat16 P2[128][72];
    float msk[32];
};

__global__ void __launch_bounds__(256) flash_attn_tc_kernel(
    const float* __restrict__ Q, int ldq,
    const float* __restrict__ Kx, const float* __restrict__ V, int ldkv,
    const float* __restrict__ mask,
    __nv_bfloat16* __restrict__ Osp, int Lq, int Lk, float scale)
{
    extern __shared__ char fsm_raw[];
    FlashSmem* sm = (FlashSmem*)fsm_raw;

    const int bh = blockIdx.y;
    const int b = bh >> 4, h = bh & 15;
    const int q0 = blockIdx.x * 128;
    const int tid = threadIdx.x, wid = tid >> 5, lane = tid & 31;
    const int r0 = lane >> 2;
    const int cc = (lane & 3) * 2;

    #pragma unroll
    for (int it = 0; it < 8; it++) {
        int idx = tid + it * 256;
        int r = idx >> 4, c4 = (idx & 15) * 4;
        float4 qv = *(const float4*)(Q + (size_t)(b*Lq + q0 + r) * ldq + h*HD + c4);
        float xs[4] = {qv.x, qv.y, qv.z, qv.w};
        unsigned short hu[4], lu[4];
        #pragma unroll
        for (int t = 0; t < 4; t++) {
            __nv_bfloat16 hh = __float2bfloat16(xs[t]);
            __nv_bfloat16 ll = __float2bfloat16(xs[t] - __bfloat162float(hh));
            hu[t] = *(unsigned short*)&hh; lu[t] = *(unsigned short*)&ll;
        }
        ushort4 h4 = {hu[0], hu[1], hu[2], hu[3]};
        ushort4 l4 = {lu[0], lu[1], lu[2], lu[3]};
        *(ushort4*)&sm->Q2[r][c4]      = h4;
        *(ushort4*)&sm->Q2[r][64 + c4] = l4;
    }

    float m0 = -1e30f, m1 = -1e30f, l0 = 0.f, l1 = 0.f;
    float o[8][4];
    #pragma unroll
    for (int d = 0; d < 8; d++)
        #pragma unroll
        for (int t = 0; t < 4; t++) o[d][t] = 0.f;

    for (int k0 = 0; k0 < Lk; k0 += 32) {
        __syncthreads();

        #pragma unroll
        for (int it = 0; it < 2; it++) {
            int idx = tid + it * 256;
            int r = idx >> 4, c4 = (idx & 15) * 4;
            const size_t grow = (size_t)(b*Lk + k0 + r) * ldkv + h*HD + c4;
            float4 kv = *(const float4*)(Kx + grow);
            float4 vv = *(const float4*)(V + grow);
            float ks[4] = {kv.x, kv.y, kv.z, kv.w};
            float vs[4] = {vv.x, vv.y, vv.z, vv.w};
            unsigned short khu[4], klu[4], vhu[4], vlu[4];
            #pragma unroll
            for (int t = 0; t < 4; t++) {
                __nv_bfloat16 hh = __float2bfloat16(ks[t]);
                __nv_bfloat16 ll = __float2bfloat16(ks[t] - __bfloat162float(hh));
                khu[t] = *(unsigned short*)&hh; klu[t] = *(unsigned short*)&ll;
                hh = __float2bfloat16(vs[t]);
                ll = __float2bfloat16(vs[t] - __bfloat162float(hh));
                vhu[t] = *(unsigned short*)&hh; vlu[t] = *(unsigned short*)&ll;
            }
            ushort4 kh4 = {khu[0], khu[1], khu[2], khu[3]};
            ushort4 kl4 = {klu[0], klu[1], klu[2], klu[3]};
            ushort4 vh4 = {vhu[0], vhu[1], vhu[2], vhu[3]};
            ushort4 vl4 = {vlu[0], vlu[1], vlu[2], vlu[3]};
            *(ushort4*)&sm->K2[r][c4]      = kh4;
            *(ushort4*)&sm->K2[r][64 + c4] = kl4;
            *(ushort4*)&sm->V2[r][c4]      = vh4;
            *(ushort4*)&sm->V2[32 + r][c4] = vl4;
        }
        if (tid < 32) sm->msk[tid] = mask ? mask[(size_t)b * Lk + k0 + tid] : 0.f;
        __syncthreads();

        float sf[4][4];
        #pragma unroll
        for (int nb = 0; nb < 4; nb++)
            #pragma unroll
            for (int t = 0; t < 4; t++) sf[nb][t] = 0.f;

        const int qc[12] = {0,16,32,48, 0,16,32,48, 64,80,96,112};
        const int kc[12] = {0,16,32,48, 64,80,96,112, 0,16,32,48};
        #pragma unroll
        for (int s = 0; s < 12; s++) {
            unsigned af[4];
            LDSM4(af[0], af[1], af[2], af[3],
                  &sm->Q2[wid*16 + (lane & 15)][qc[s] + (lane >> 4) * 8]);
            #pragma unroll
            for (int nb = 0; nb < 2; nb++) {
                unsigned t0, t1, t2, t3;
                LDSM4(t0, t1, t2, t3,
                      &sm->K2[nb*16 + (lane & 15)][kc[s] + (lane >> 4) * 8]);
                MMA16816(sf[nb*2],     af[0], af[1], af[2], af[3], t0, t2);
                MMA16816(sf[nb*2 + 1], af[0], af[1], af[2], af[3], t1, t3);
            }
        }

        #pragma unroll
        for (int nb = 0; nb < 4; nb++) {
            float mv0 = sm->msk[nb*8 + cc], mv1 = sm->msk[nb*8 + cc + 1];
            sf[nb][0] = sf[nb][0] * scale + mv0;
            sf[nb][1] = sf[nb][1] * scale + mv1;
            sf[nb][2] = sf[nb][2] * scale + mv0;
            sf[nb][3] = sf[nb][3] * scale + mv1;
        }

        float tm0 = -1e30f, tm1 = -1e30f;
        #pragma unroll
        for (int nb = 0; nb < 4; nb++) {
            tm0 = fmaxf(tm0, fmaxf(sf[nb][0], sf[nb][1]));
            tm1 = fmaxf(tm1, fmaxf(sf[nb][2], sf[nb][3]));
        }
        tm0 = fmaxf(tm0, __shfl_xor_sync(0xffffffffu, tm0, 1));
        tm0 = fmaxf(tm0, __shfl_xor_sync(0xffffffffu, tm0, 2));
        tm1 = fmaxf(tm1, __shfl_xor_sync(0xffffffffu, tm1, 1));
        tm1 = fmaxf(tm1, __shfl_xor_sync(0xffffffffu, tm1, 2));

        const float nm0 = fmaxf(m0, tm0), nm1 = fmaxf(m1, tm1);
        const float corr0 = __expf(m0 - nm0), corr1 = __expf(m1 - nm1);
        m0 = nm0; m1 = nm1;

        float ts0 = 0.f, ts1 = 0.f;
        #pragma unroll
        for (int nb = 0; nb < 4; nb++) {
            sf[nb][0] = __expf(sf[nb][0] - nm0);
            sf[nb][1] = __expf(sf[nb][1] - nm0);
            sf[nb][2] = __expf(sf[nb][2] - nm1);
            sf[nb][3] = __expf(sf[nb][3] - nm1);
            ts0 += sf[nb][0] + sf[nb][1];
            ts1 += sf[nb][2] + sf[nb][3];
        }
        ts0 += __shfl_xor_sync(0xffffffffu, ts0, 1);
        ts0 += __shfl_xor_sync(0xffffffffu, ts0, 2);
        ts1 += __shfl_xor_sync(0xffffffffu, ts1, 1);
        ts1 += __shfl_xor_sync(0xffffffffu, ts1, 2);
        l0 = l0 * corr0 + ts0;
        l1 = l1 * corr1 + ts1;

        const int pr0 = wid*16 + r0, pr1 = pr0 + 8;
        #pragma unroll
        for (int nb = 0; nb < 4; nb++) {
            #pragma unroll
            for (int half = 0; half < 2; half++) {
                const int prow = half ? pr1 : pr0;
                float p0 = sf[nb][half*2], p1 = sf[nb][half*2 + 1];
                __nv_bfloat16 h0 = __float2bfloat16(p0);
                __nv_bfloat16 h1 = __float2bfloat16(p1);
                __nv_bfloat16 e0 = __float2bfloat16(p0 - __bfloat162float(h0));
                __nv_bfloat16 e1 = __float2bfloat16(p1 - __bfloat162float(h1));
                unsigned ph = (unsigned)*(unsigned short*)&h0 |
                              ((unsigned)*(unsigned short*)&h1 << 16);
                unsigned pl = (unsigned)*(unsigned short*)&e0 |
                              ((unsigned)*(unsigned short*)&e1 << 16);
                *(unsigned*)&sm->P2[prow][nb*8 + cc]      = ph;
                *(unsigned*)&sm->P2[prow][32 + nb*8 + cc] = pl;
            }
        }

        #pragma unroll
        for (int d = 0; d < 8; d++) {
            o[d][0] *= corr0; o[d][1] *= corr0;
            o[d][2] *= corr1; o[d][3] *= corr1;
        }
        __syncthreads();

        const int pc[6] = {0, 16, 32, 48, 0, 16};
        const int vc[6] = {0, 16, 0, 16, 32, 48};
        #pragma unroll
        for (int s = 0; s < 6; s++) {
            unsigned af[4];
            LDSM4(af[0], af[1], af[2], af[3],
                  &sm->P2[wid*16 + (lane & 15)][pc[s] + (lane >> 4) * 8]);
            #pragma unroll
            for (int p = 0; p < 4; p++) {
                unsigned t0, t1, t2, t3;
                int krow = vc[s] + (lane & 7) + ((lane >> 3) & 1) * 8;
                int ncol = p*16 + (lane >> 4) * 8;
                LDSM4T(t0, t1, t2, t3, &sm->V2[krow][ncol]);
                MMA16816(o[p*2],     af[0], af[1], af[2], af[3], t0, t1);
                MMA16816(o[p*2 + 1], af[0], af[1], af[2], af[3], t2, t3);
            }
        }
    }

    const float li0 = 1.f / l0, li1 = 1.f / l1;
    const int gq0 = b*Lq + q0 + wid*16 + r0;
    #pragma unroll
    for (int d = 0; d < 8; d++) {
        const int col = h*HD + d*8 + cc;
        emit_split_pair(Osp + (size_t)gq0 * (3*D),       D, col, o[d][0]*li0, o[d][1]*li0);
        emit_split_pair(Osp + (size_t)(gq0 + 8) * (3*D), D, col, o[d][2]*li1, o[d][3]*li1);
    }
}

// ================= residual + LayerNorm (optional split emission) =================
__global__ void __launch_bounds__(256) ln_residual_kernel(
    const float* __restrict__ Y, const float* __restrict__ R,
    const float* __restrict__ g, const float* __restrict__ be,
    float* __restrict__ O, __nv_bfloat16* __restrict__ Sp)
{
    const size_t row = blockIdx.x;
    const int tid = threadIdx.x;
    const float* y = Y + row * D;
    const float* r = R + row * D;
    __shared__ float red[256];

    float h[4];
    float s = 0.f;
    #pragma unroll
    for (int i = 0; i < 4; i++) {
        h[i] = y[tid + i*256] + r[tid + i*256];
        s += h[i];
    }
    red[tid] = s; __syncthreads();
    for (int st = 128; st > 0; st >>= 1) {
        if (tid < st) red[tid] += red[tid + st];
        __syncthreads();
    }
    const float mean = red[0] * (1.0f / D);
    __syncthreads();

    float vs = 0.f;
    #pragma unroll
    for (int i = 0; i < 4; i++) {
        float dd = h[i] - mean;
        vs += dd * dd;
    }
    red[tid] = vs; __syncthreads();
    for (int st = 128; st > 0; st >>= 1) {
        if (tid < st) red[tid] += red[tid + st];
        __syncthreads();
    }
    const float inv = rsqrtf(red[0] * (1.0f / D) + 1e-5f);

    __nv_bfloat16* sprow = Sp ? Sp + row * (size_t)(3 * D) : nullptr;
    #pragma unroll
    for (int i = 0; i < 4; i++) {
        const int c = tid + i*256;
        const float v = (h[i] - mean) * inv * g[c] + be[c];
        O[row * D + c] = v;
        if (sprow) {
            __nv_bfloat16 hh = __float2bfloat16(v);
            __nv_bfloat16 ll = __float2bfloat16(v - __bfloat162float(hh));
            sprow[c]         = hh;
            sprow[D + c]     = hh;
            sprow[2 * D + c] = ll;
        }
    }
}

// ================= host launch =================
extern "C" void kernel_launch(void* const* d_in, const int* in_sizes, int n_in,
                              void* d_out, int out_size)
{
    const float* input = (const float*)d_in[0];
    const float* ctx   = (const float*)d_in[1];
    const float* mask  = (const float*)d_in[2];
    const float* cq_w = (const float*)d_in[3];  const float* cq_b = (const float*)d_in[4];
    const float* ck_w = (const float*)d_in[5];  const float* ck_b = (const float*)d_in[6];
    const float* cv_w = (const float*)d_in[7];  const float* cv_b = (const float*)d_in[8];
    const float* co_w = (const float*)d_in[9];  const float* co_b = (const float*)d_in[10];
    const float* co_g = (const float*)d_in[11]; const float* co_be= (const float*)d_in[12];
    const float* sq_w = (const float*)d_in[13]; const float* sq_b = (const float*)d_in[14];
    const float* sk_w = (const float*)d_in[15]; const float* sk_b = (const float*)d_in[16];
    const float* sv_w = (const float*)d_in[17]; const float* sv_b = (const float*)d_in[18];
    const float* so_w = (const float*)d_in[19]; const float* so_b = (const float*)d_in[20];
    const float* so_g = (const float*)d_in[21]; const float* so_be= (const float*)d_in[22];
    const float* fi_w = (const float*)d_in[23]; const float* fi_b = (const float*)d_in[24];
    const float* fo_w = (const float*)d_in[25]; const float* fo_b = (const float*)d_in[26];
    const float* fo_g = (const float*)d_in[27]; const float* fo_be= (const float*)d_in[28];

    float *q, *kv, *x, *x2, *y;
    __nv_bfloat16 *sa, *sa2, *sb;
    cudaGetSymbolAddress((void**)&q,    g_q);
    cudaGetSymbolAddress((void**)&kv,   g_kv);
    cudaGetSymbolAddress((void**)&x,    g_x);
    cudaGetSymbolAddress((void**)&x2,   g_x2);
    cudaGetSymbolAddress((void**)&y,    g_y);
    cudaGetSymbolAddress((void**)&sa,   g_sa);
    cudaGetSymbolAddress((void**)&sa2,  g_sa2);
    cudaGetSymbolAddress((void**)&sb,   g_sb);

    const float scale = 0.125f; // 1/sqrt(64)
    dim3 blk(256);
    const int FLASH_SMEM = (int)sizeof(FlashSmem);
    static int smem_set = 0;
    if (!smem_set) {
        cudaFuncSetAttribute(flash_attn_tc_kernel,
                             cudaFuncAttributeMaxDynamicSharedMemorySize, FLASH_SMEM);
        cudaFuncSetAttribute(hgemm_kernel<0,0,1>,
                             cudaFuncAttributeMaxDynamicSharedMemorySize, HG_SMEM);
        cudaFuncSetAttribute(hgemm_kernel<0,0,2>,
                             cudaFuncAttributeMaxDynamicSharedMemorySize, HG_SMEM);
        cudaFuncSetAttribute(hgemm_kernel<0,0,3>,
                             cudaFuncAttributeMaxDynamicSharedMemorySize, HG_SMEM);
        cudaFuncSetAttribute(hgemm_kernel<1,1,1>,
                             cudaFuncAttributeMaxDynamicSharedMemorySize, HG_SMEM);
        smem_set = 1;
    }

    #define SPLIT_A(X, R, C, SH) split_a_kernel<<<((size_t)(R)*(C))/1024, blk>>>((X), sa2, (C)-1, (SH))
    #define SPLIT_B(W, K_, N_, SH, C0, NT) \
        split_b_kernel<<<((size_t)(K_)*(N_))/1024, blk>>>((W), sb, (K_), (N_)-1, (SH), (C0), (NT))

    // ---- cross attention ----
    SPLIT_A(input, MQ, D, 10);
    SPLIT_B(cq_w, D, D, 10, 0, D);
    hgemm_kernel<0,0,1><<<dim3(D/128, MQ/128), blk, HG_SMEM>>>(
        sa2, sb, cq_b, nullptr, nullptr, q, nullptr, D, 3*D);

    SPLIT_A(ctx, MCTX, D, 10);
    SPLIT_B(ck_w, D, D, 10, 0, 2*D);
    SPLIT_B(cv_w, D, D, 10, D, 2*D);
    hgemm_kernel<0,0,2><<<dim3((2*D)/128, MCTX/128), blk, HG_SMEM>>>(
        sa2, sb, ck_b, cv_b, nullptr, kv, nullptr, 2*D, 3*D);

    flash_attn_tc_kernel<<<dim3(LQ/128, B*H), blk, FLASH_SMEM>>>(
        q, D, kv, kv + D, 2*D, mask, sa2, LQ, LK, scale);

    SPLIT_B(co_w, D, D, 10, 0, D);
    hgemm_kernel<0,0,1><<<dim3(D/128, MQ/128), blk, HG_SMEM>>>(
        sa2, sb, co_b, nullptr, nullptr, y, nullptr, D, 3*D);
    ln_residual_kernel<<<MQ, blk>>>(y, input, co_g, co_be, x, sa2);   // emits x split

    // ---- self attention (fused QKV, N=3072) ----
    SPLIT_B(sq_w, D, D, 10, 0,   3*D);
    SPLIT_B(sk_w, D, D, 10, D,   3*D);
    SPLIT_B(sv_w, D, D, 10, 2*D, 3*D);
    hgemm_kernel<0,0,3><<<dim3((3*D)/128, MQ/128), blk, HG_SMEM>>>(
        sa2, sb, sq_b, sk_b, sv_b, kv, nullptr, 3*D, 3*D);

    flash_attn_tc_kernel<<<dim3(LQ/128, B*H), blk, FLASH_SMEM>>>(
        kv, 3*D, kv + D, kv + 2*D, 3*D, nullptr, sa2, LQ, LQ, scale);

    SPLIT_B(so_w, D, D, 10, 0, D);
    hgemm_kernel<0,0,1><<<dim3(D/128, MQ/128), blk, HG_SMEM>>>(
        sa2, sb, so_b, nullptr, nullptr, y, nullptr, D, 3*D);
    ln_residual_kernel<<<MQ, blk>>>(y, x, so_g, so_be, x2, sa2);      // emits x2 split

    // ---- FFN ----
    SPLIT_B(fi_w, D, F, 12, 0, F);
    hgemm_kernel<1,1,1><<<dim3(F/128, MQ/128), blk, HG_SMEM>>>(
        sa2, sb, fi_b, nullptr, nullptr, nullptr, sa, F, 3*D);
    SPLIT_B(fo_w, F, D, 10, 0, D);
    hgemm_kernel<0,0,1><<<dim3(D/128, MQ/128), blk, HG_SMEM>>>(
        sa, sb, fo_b, nullptr, nullptr, y, nullptr, D, 3*F);
    ln_residual_kernel<<<MQ, blk>>>(y, x2, fo_g, fo_be, (float*)d_out, nullptr);

    #undef SPLIT_A
    #undef SPLIT_B
}